// round 11
// baseline (speedup 1.0000x reference)
#include <cuda_runtime.h>
#include <cuda_fp16.h>
#include <math.h>
#include <stdint.h>

// Problem constants
#define Bb   2
#define Tt   2048
#define Cc   1024
#define Hh   16
#define DHd  64
#define Mrows (Bb * Tt)          // 4096
#define QKV_N (3 * Cc)           // 3072
#define FFN_N (4 * Cc)           // 4096
#define ATT_SCALE 0.03125f       // C^-0.5 = 1/32
#define LN_EPS 1e-5f

// ---------------------------------------------------------------------------
// Scratch (static device allocations; no cudaMalloc allowed)
// ---------------------------------------------------------------------------
__device__ __half g_x1  [Mrows * Cc];
__device__ __half g_qkv [Mrows * QKV_N];
__device__ __half g_vT  [Bb * Hh * DHd * Tt];
__device__ __half g_attn[Mrows * Cc];
__device__ float  g_y   [Mrows * Cc];
__device__ __half g_x2  [Mrows * Cc];
__device__ __half g_h   [Mrows * FFN_N];
__device__ __half g_wqkv[QKV_N * Cc];
__device__ __half g_wo  [Cc * Cc];
__device__ __half g_w1  [FFN_N * Cc];
__device__ __half g_w2  [Cc * FFN_N];

// ---------------------------------------------------------------------------
// Helpers
// ---------------------------------------------------------------------------
__device__ __forceinline__ void cp_async16(void* smem, const void* gmem) {
    unsigned saddr = (unsigned)__cvta_generic_to_shared(smem);
    asm volatile("cp.async.cg.shared.global [%0], [%1], 16;\n"
                 :: "r"(saddr), "l"(gmem));
}
__device__ __forceinline__ void cp_async_commit() {
    asm volatile("cp.async.commit_group;\n" ::: "memory");
}
__device__ __forceinline__ void cp_async_wait0() {
    asm volatile("cp.async.wait_group 0;\n" ::: "memory");
}
__device__ __forceinline__ void cp_async_wait1() {
    asm volatile("cp.async.wait_group 1;\n" ::: "memory");
}

// fp16 mma: m16n8k16, fp32 accum
__device__ __forceinline__ void mma_f16(float c[4],
                                        const uint32_t a[4],
                                        const uint32_t b[2]) {
    asm volatile(
        "mma.sync.aligned.m16n8k16.row.col.f32.f16.f16.f32 "
        "{%0,%1,%2,%3}, {%4,%5,%6,%7}, {%8,%9}, {%0,%1,%2,%3};\n"
        : "+f"(c[0]), "+f"(c[1]), "+f"(c[2]), "+f"(c[3])
        : "r"(a[0]), "r"(a[1]), "r"(a[2]), "r"(a[3]),
          "r"(b[0]), "r"(b[1]));
}
__device__ __forceinline__ uint32_t pack_h2(float a, float b) {
    __half2 h = __floats2half2_rn(a, b);
    return *(uint32_t*)&h;
}
__device__ __forceinline__ void ldsm4(uint32_t r[4], uint32_t saddr) {
    asm volatile("ldmatrix.sync.aligned.m8n8.x4.shared.b16 {%0,%1,%2,%3}, [%4];"
                 : "=r"(r[0]), "=r"(r[1]), "=r"(r[2]), "=r"(r[3])
                 : "r"(saddr));
}

// ---------------------------------------------------------------------------
// Fused weight prep (kept from Round 10 — harmless, 1 launch instead of 4)
// ---------------------------------------------------------------------------
__device__ __forceinline__ void tile_transpose_h(
    const float* __restrict__ in, __half* __restrict__ out,
    int R, int Cn, int r0, int c0, float scl) {
    __shared__ float t[32][33];
    int x = threadIdx.x, y = threadIdx.y;
#pragma unroll
    for (int i = 0; i < 32; i += 8)
        t[y + i][x] = in[(size_t)(r0 + y + i) * Cn + c0 + x];
    __syncthreads();
#pragma unroll
    for (int i = 0; i < 32; i += 8)
        out[(size_t)(c0 + y + i) * R + r0 + x] = __float2half(t[x][y + i] * scl);
}

__global__ __launch_bounds__(256)
void prep_weights_kernel(const float* __restrict__ Wq,
                         const float* __restrict__ Wk,
                         const float* __restrict__ Wv,
                         const float* __restrict__ Wo,
                         const float* __restrict__ W1,
                         const float* __restrict__ W2) {
    int bid = blockIdx.x;
    if (bid < 3072) {
        int zh  = bid >> 6;
        int rem = bid & 63;
        int cb = rem & 31, db = rem >> 5;
        int sel = zh >> 4, h = zh & 15;
        const float* W = (sel == 0) ? Wq : (sel == 1) ? Wk : Wv;
        float scl = (sel == 0) ? ATT_SCALE : 1.0f;
        __shared__ float t[32][33];
        int x = threadIdx.x, y = threadIdx.y;
        int c0 = cb * 32, d0 = db * 32;
#pragma unroll
        for (int i = 0; i < 32; i += 8)
            t[y + i][x] = W[(size_t)(h * Cc + c0 + y + i) * DHd + d0 + x];
        __syncthreads();
#pragma unroll
        for (int i = 0; i < 32; i += 8)
            g_wqkv[(size_t)(sel * Cc + h * DHd + d0 + y + i) * Cc + c0 + x] =
                __float2half(t[x][y + i] * scl);
    } else if (bid < 4096) {
        int r = bid - 3072;
        int cb = r & 31, rb = r >> 5;
        tile_transpose_h(Wo, g_wo, Cc, Cc, rb * 32, cb * 32, 1.0f);
    } else if (bid < 8192) {
        int r = bid - 4096;
        int cb = r & 127, rb = r >> 7;
        tile_transpose_h(W1, g_w1, Cc, FFN_N, rb * 32, cb * 32, 1.0f);
    } else {
        int r = bid - 8192;
        int cb = r & 31, rb = r >> 5;
        tile_transpose_h(W2, g_w2, FFN_N, Cc, rb * 32, cb * 32, 1.0f);
    }
}

// V slice of qkv -> g_vT [(b*Hh+h)*64 + d][t]
__global__ __launch_bounds__(256)
void transpose_v_kernel(const __half* __restrict__ qkv,
                        __half* __restrict__ vT) {
    __shared__ __half t[32][33];
    int t0 = blockIdx.x * 32, d0 = blockIdx.y * 32;
    int z = blockIdx.z;
    int b = z >> 4, h = z & 15;
    int x = threadIdx.x, y = threadIdx.y;
#pragma unroll
    for (int i = 0; i < 32; i += 8)
        t[y + i][x] = qkv[(size_t)(b * Tt + t0 + y + i) * QKV_N
                          + 2 * Cc + h * DHd + d0 + x];
    __syncthreads();
#pragma unroll
    for (int i = 0; i < 32; i += 8)
        vT[(size_t)((b * Hh + h) * DHd + d0 + y + i) * Tt + t0 + x] = t[x][y + i];
}

// ---------------------------------------------------------------------------
// LayerNorm over axis 1 (TIME), unbiased variance. fp16 out. 1024 thr/block.
// ---------------------------------------------------------------------------
__global__ __launch_bounds__(1024)
void ln_axis1_kernel(const float* __restrict__ x,
                     const float* __restrict__ gamma,
                     const float* __restrict__ beta,
                     __half* __restrict__ out) {
    int b  = blockIdx.y;
    int tx = threadIdx.x, ty = threadIdx.y;
    int c  = blockIdx.x * 32 + tx;
    const float* xp = x + (size_t)b * Tt * Cc + c;

    float s = 0.f, s2 = 0.f;
    for (int t = ty; t < Tt; t += 32) {
        float v = xp[(size_t)t * Cc];
        s += v; s2 += v * v;
    }
    __shared__ float ss[32][32], sq[32][32];
    __shared__ float smean[32], srstd[32];
    ss[ty][tx] = s; sq[ty][tx] = s2;
    __syncthreads();
    if (ty == 0) {
        float S = 0.f, S2 = 0.f;
#pragma unroll
        for (int k = 0; k < 32; k++) { S += ss[k][tx]; S2 += sq[k][tx]; }
        float mean = S / (float)Tt;
        float var  = (S2 - (float)Tt * mean * mean) / (float)(Tt - 1);
        smean[tx] = mean;
        srstd[tx] = rsqrtf(var + LN_EPS);
    }
    __syncthreads();
    float mean = smean[tx], rstd = srstd[tx];
    float g = gamma[c], be = beta[c];
    __half* op = out + (size_t)b * Tt * Cc + c;
    for (int t = ty; t < Tt; t += 32) {
        op[(size_t)t * Cc] = __float2half(g * (xp[(size_t)t * Cc] - mean) * rstd + be);
    }
}

// ---------------------------------------------------------------------------
// FP16 mma.sync GEMM, ldmatrix fragments, 3-stage cp.async (Round-9 PASS).
// ---------------------------------------------------------------------------
#define HSTR 40
#define TILE_H (128 * HSTR)
#define STG_H  (2 * TILE_H)
#define NSTG 3
#define GEMM_SMEM (NSTG * STG_H * 2)

template<bool BIAS, bool RELU, bool RES, bool OUTH>
__global__ __launch_bounds__(256, 2)
void gemm_f16_kernel(const __half* __restrict__ A,
                     const __half* __restrict__ Bt,
                     const float* __restrict__ bias,
                     const float* __restrict__ res,
                     void* __restrict__ CoutV,
                     int M, int N, int K) {
    extern __shared__ __half smh[];

    const int tid  = threadIdx.x;
    const int lane = tid & 31;
    const int warp = tid >> 5;
    const int wm   = warp >> 1;
    const int wn   = warp & 1;
    const int gid  = lane >> 2;
    const int tid4 = lane & 3;

    const int lrow = lane & 7;
    const int q    = lane >> 3;
    const int arow = (q & 1) * 8 + lrow;
    const int akof = (q >> 1) * 8;
    const int brow = (q >> 1) * 8 + lrow;
    const int bkof = (q & 1) * 8;

    const int row0 = blockIdx.y * 128;
    const int col0 = blockIdx.x * 128;
    const int nIter = K >> 5;

    const uint32_t sm_u = (uint32_t)__cvta_generic_to_shared(smh);

    float acc[2][8][4];
#pragma unroll
    for (int i = 0; i < 2; i++)
#pragma unroll
        for (int j = 0; j < 8; j++)
#pragma unroll
            for (int qq = 0; qq < 4; qq++) acc[i][j][qq] = 0.f;

    auto load_stage = [&](int s, int kc) {
        __half* as = smh + s * STG_H;
        __half* bs = as + TILE_H;
        const __half* ap = A  + (size_t)row0 * K + kc * 32;
        const __half* bp = Bt + (size_t)col0 * K + kc * 32;
#pragma unroll
        for (int qq = 0; qq < 2; qq++) {
            int id = tid + 256 * qq;
            int r = id >> 2, c8 = (id & 3) << 3;
            cp_async16(&as[r * HSTR + c8], ap + (size_t)r * K + c8);
        }
#pragma unroll
        for (int qq = 0; qq < 2; qq++) {
            int id = tid + 256 * qq;
            int r = id >> 2, c8 = (id & 3) << 3;
            cp_async16(&bs[r * HSTR + c8], bp + (size_t)r * K + c8);
        }
        cp_async_commit();
    };

    load_stage(0, 0);
    load_stage(1, 1);

    for (int it = 0; it < nIter; ++it) {
        cp_async_wait1();
        __syncthreads();

        if (it + 2 < nIter) load_stage((it + 2) % NSTG, it + 2);
        else                cp_async_commit();

        const int s = it % NSTG;
        const uint32_t as_u = sm_u + (s * STG_H) * 2;
        const uint32_t bs_u = as_u + TILE_H * 2;

#pragma unroll
        for (int ks = 0; ks < 2; ks++) {
            const int k0 = ks * 16;
            uint32_t af[2][4];
#pragma unroll
            for (int i = 0; i < 2; i++)
                ldsm4(af[i], as_u + ((wm * 32 + i * 16 + arow) * HSTR
                                     + k0 + akof) * 2);
            uint32_t bf[8][2];
#pragma unroll
            for (int jp = 0; jp < 4; jp++) {
                uint32_t t4[4];
                ldsm4(t4, bs_u + ((wn * 64 + 16 * jp + brow) * HSTR
                                  + k0 + bkof) * 2);
                bf[2 * jp][0]     = t4[0];
                bf[2 * jp][1]     = t4[1];
                bf[2 * jp + 1][0] = t4[2];
                bf[2 * jp + 1][1] = t4[3];
            }
#pragma unroll
            for (int i = 0; i < 2; i++)
#pragma unroll
                for (int j = 0; j < 8; j++)
                    mma_f16(acc[i][j], af[i], bf[j]);
        }
    }

    float*  Cf = (float*)CoutV;
    __half* Ch = (__half*)CoutV;
#pragma unroll
    for (int i = 0; i < 2; i++) {
#pragma unroll
        for (int hr = 0; hr < 2; hr++) {
            int r = row0 + wm * 32 + i * 16 + hr * 8 + gid;
#pragma unroll
            for (int j = 0; j < 8; j++) {
                int cI = col0 + wn * 64 + j * 8 + 2 * tid4;
                float v0 = acc[i][j][hr * 2];
                float v1 = acc[i][j][hr * 2 + 1];
                if (BIAS) {
                    float2 bi = *(const float2*)&bias[cI];
                    v0 += bi.x; v1 += bi.y;
                }
                if (RES) {
                    float2 rv = *(const float2*)&res[(size_t)r * N + cI];
                    v0 += rv.x; v1 += rv.y;
                }
                if (RELU) { v0 = fmaxf(v0, 0.f); v1 = fmaxf(v1, 0.f); }
                if (OUTH) {
                    *(__half2*)&Ch[(size_t)r * N + cI] = __floats2half2_rn(v0, v1);
                } else {
                    *(float2*)&Cf[(size_t)r * N + cI] = make_float2(v0, v1);
                }
            }
        }
    }
}

// ---------------------------------------------------------------------------
// Causal flash attention, fp16 mma + ldmatrix, register-direct P.
// BQ=128 per CTA, 256 threads = 8 warps (warp w owns rows 16w..16w+15),
// BS=64 K/V tiles shared by all warps. 2 CTAs/SM -> 16 warps/SM.
// Heaviest CTAs launch first (qt reversed).
// ---------------------------------------------------------------------------
#define AST 72
#define ATT_SMEM ((128 + 128 + 128) * AST * 2)   // 55296 B

__global__ __launch_bounds__(256, 2)
void attn_f16_kernel(const __half* __restrict__ qkv,
                     const __half* __restrict__ vT,
                     __half* __restrict__ outp) {
    extern __shared__ __half sha[];
    __half* Qs = sha;                   // [128][AST]
    __half* Ks = Qs + 128 * AST;        // [2][64][AST]
    __half* Vs = Ks + 2 * 64 * AST;     // [2][64][AST]  (rows = d, cols = s)

    const int qt = (int)gridDim.x - 1 - (int)blockIdx.x;   // heavy first
    const int h = blockIdx.y, b = blockIdx.z;
    const int t0 = qt * 128;
    const int tid  = threadIdx.x;
    const int lane = tid & 31;
    const int warp = tid >> 5;          // 0..7
    const int gid  = lane >> 2;
    const int tid4 = lane & 3;
    const unsigned FULL = 0xffffffffu;

    const int lrow = lane & 7;
    const int q    = lane >> 3;
    const int arow = (q & 1) * 8 + lrow;
    const int akof = (q >> 1) * 8;
    const int brow = (q >> 1) * 8 + lrow;
    const int bkof = (q & 1) * 8;

    const uint32_t sm_u = (uint32_t)__cvta_generic_to_shared(sha);
    const uint32_t Qs_u = sm_u;
    const uint32_t Ks_u = sm_u + 128 * AST * 2;
    const uint32_t Vs_u = Ks_u + 2 * 64 * AST * 2;

    const __half* qb = qkv + (size_t)(b * Tt) * QKV_N + h * DHd;
    const __half* kb = qkv + (size_t)(b * Tt) * QKV_N + Cc + h * DHd;
    const __half* vb = vT + (size_t)((b * Hh + h) * DHd) * Tt;

    // prefetch Q tile (128 rows) + K0/V0 (64 rows each)
#pragma unroll
    for (int qq = 0; qq < 4; qq++) {
        int id  = tid + 256 * qq;       // 0..1023
        int row = id >> 3;
        int c8  = (id & 7) * 8;
        cp_async16(&Qs[row * AST + c8], qb + (size_t)(t0 + row) * QKV_N + c8);
    }
#pragma unroll
    for (int qq = 0; qq < 2; qq++) {
        int id  = tid + 256 * qq;       // 0..511
        int row = id >> 3;
        int c8  = (id & 7) * 8;
        cp_async16(&Ks[row * AST + c8], kb + (size_t)row * QKV_N + c8);
        cp_async16(&Vs[row * AST + c8], vb + (size_t)row * Tt + c8);
    }
    cp_async_commit();
    cp_async_wait0();
    __syncthreads();

    uint32_t qa[4][4];
#pragma unroll
    for (int ks = 0; ks < 4; ks++)
        ldsm4(qa[ks], Qs_u + ((16 * warp + arow) * AST + 16 * ks + akof) * 2);

    float m0 = -1e30f, m1 = -1e30f, l0 = 0.f, l1 = 0.f;
    float o[8][4];
#pragma unroll
    for (int j = 0; j < 8; j++)
#pragma unroll
        for (int qq = 0; qq < 4; qq++) o[j][qq] = 0.f;

    const int rg0 = t0 + 16 * warp + gid;   // this thread's global rows (and +8)
    const int nt = 2 * qt + 2;              // s-tiles of 64 covering [0, t0+128)
    for (int it = 0; it < nt; ++it) {
        const int buf = it & 1;
        const uint32_t Kb_u = Ks_u + buf * 64 * AST * 2;
        const uint32_t Vb_u = Vs_u + buf * 64 * AST * 2;

        cp_async_wait0();
        __syncthreads();

        if (it + 1 < nt) {
            const int s0 = (it + 1) * 64;
            __half* Kn = Ks + (buf ^ 1) * 64 * AST;
            __half* Vn = Vs + (buf ^ 1) * 64 * AST;
#pragma unroll
            for (int qq = 0; qq < 2; qq++) {
                int id  = tid + 256 * qq;
                int row = id >> 3;
                int c8  = (id & 7) * 8;
                cp_async16(&Kn[row * AST + c8],
                           kb + (size_t)(s0 + row) * QKV_N + c8);
                cp_async16(&Vn[row * AST + c8],
                           vb + (size_t)row * Tt + s0 + c8);
            }
            cp_async_commit();
        }

        // ---- S = Q K^T ----
        float sc[8][4];
#pragma unroll
        for (int j = 0; j < 8; j++)
#pragma unroll
            for (int qq = 0; qq < 4; qq++) sc[j][qq] = 0.f;
#pragma unroll
        for (int ks = 0; ks < 4; ks++) {
            uint32_t kf[8][2];
#pragma unroll
            for (int jp = 0; jp < 4; jp++) {
                uint32_t t4[4];
                ldsm4(t4, Kb_u + ((16 * jp + brow) * AST + 16 * ks + bkof) * 2);
                kf[2 * jp][0]     = t4[0];
                kf[2 * jp][1]     = t4[1];
                kf[2 * jp + 1][0] = t4[2];
                kf[2 * jp + 1][1] = t4[3];
            }
#pragma unroll
            for (int j = 0; j < 8; j++)
                mma_f16(sc[j], qa[ks], kf[j]);
        }

        // ---- causal mask (last two s-tiles only), global coordinates ----
        if (it * 64 >= t0) {
            const int sg0 = it * 64;
#pragma unroll
            for (int j = 0; j < 8; j++) {
                int cg = sg0 + 8 * j + 2 * tid4;
                if (cg     > rg0)     sc[j][0] = -1e30f;
                if (cg + 1 > rg0)     sc[j][1] = -1e30f;
                if (cg     > rg0 + 8) sc[j][2] = -1e30f;
                if (cg + 1 > rg0 + 8) sc[j][3] = -1e30f;
            }
        }

        // ---- online softmax ----
        float mx0 = -1e30f, mx1 = -1e30f;
#pragma unroll
        for (int j = 0; j < 8; j++) {
            mx0 = fmaxf(mx0, fmaxf(sc[j][0], sc[j][1]));
            mx1 = fmaxf(mx1, fmaxf(sc[j][2], sc[j][3]));
        }
        mx0 = fmaxf(mx0, __shfl_xor_sync(FULL, mx0, 1));
        mx0 = fmaxf(mx0, __shfl_xor_sync(FULL, mx0, 2));
        mx1 = fmaxf(mx1, __shfl_xor_sync(FULL, mx1, 1));
        mx1 = fmaxf(mx1, __shfl_xor_sync(FULL, mx1, 2));
        float mn0 = fmaxf(m0, mx0), mn1 = fmaxf(m1, mx1);
        float sum0 = 0.f, sum1 = 0.f;
#pragma unroll
        for (int j = 0; j < 8; j++) {
            sc[j][0] = __expf(sc[j][0] - mn0);
            sc[j][1] = __expf(sc[j][1] - mn0);
            sc[j][2] = __expf(sc[j][2] - mn1);
            sc[j][3] = __expf(sc[j][3] - mn1);
            sum0 += sc[j][0] + sc[j][1];
            sum1 += sc[j][2] + sc[j][3];
        }
        sum0 += __shfl_xor_sync(FULL, sum0, 1);
        sum0 += __shfl_xor_sync(FULL, sum0, 2);
        sum1 += __shfl_xor_sync(FULL, sum1, 1);
        sum1 += __shfl_xor_sync(FULL, sum1, 2);
        float c0 = __expf(m0 - mn0), c1 = __expf(m1 - mn1);
        l0 = l0 * c0 + sum0;
        l1 = l1 * c1 + sum1;
        m0 = mn0; m1 = mn1;
#pragma unroll
        for (int j = 0; j < 8; j++) {
            o[j][0] *= c0; o[j][1] *= c0;
            o[j][2] *= c1; o[j][3] *= c1;
        }

        // ---- O += P V : P packs directly from sc registers ----
#pragma unroll
        for (int ks = 0; ks < 4; ks++) {
            uint32_t pa[4];
            pa[0] = pack_h2(sc[2 * ks][0],     sc[2 * ks][1]);
            pa[1] = pack_h2(sc[2 * ks][2],     sc[2 * ks][3]);
            pa[2] = pack_h2(sc[2 * ks + 1][0], sc[2 * ks + 1][1]);
            pa[3] = pack_h2(sc[2 * ks + 1][2], sc[2 * ks + 1][3]);
            uint32_t vf[8][2];
#pragma unroll
            for (int jp = 0; jp < 4; jp++) {
                uint32_t t4[4];
                ldsm4(t4, Vb_u + ((16 * jp + brow) * AST + 16 * ks + bkof) * 2);
                vf[2 * jp][0]     = t4[0];
                vf[2 * jp][1]     = t4[1];
                vf[2 * jp + 1][0] = t4[2];
                vf[2 * jp + 1][1] = t4[3];
            }
#pragma unroll
            for (int j = 0; j < 8; j++)
                mma_f16(o[j], pa, vf[j]);
        }
    }

    float inv0 = 1.f / l0, inv1 = 1.f / l1;
#pragma unroll
    for (int j = 0; j < 8; j++) {
        int cI = h * DHd + 8 * j + 2 * tid4;
        __half2 v0 = __floats2half2_rn(o[j][0] * inv0, o[j][1] * inv0);
        __half2 v1 = __floats2half2_rn(o[j][2] * inv1, o[j][3] * inv1);
        *(__half2*)&outp[(size_t)(b * Tt + rg0) * Cc + cI]     = v0;
        *(__half2*)&outp[(size_t)(b * Tt + rg0 + 8) * Cc + cI] = v1;
    }
}

// ---------------------------------------------------------------------------
// Launch
// ---------------------------------------------------------------------------
extern "C" void kernel_launch(void* const* d_in, const int* in_sizes, int n_in,
                              void* d_out, int out_size) {
    const float* x      = (const float*)d_in[0];
    const float* Wq     = (const float*)d_in[1];
    const float* Wk     = (const float*)d_in[2];
    const float* Wv     = (const float*)d_in[3];
    const float* Wo     = (const float*)d_in[4];
    const float* bo     = (const float*)d_in[5];
    const float* W1     = (const float*)d_in[6];
    const float* b1     = (const float*)d_in[7];
    const float* W2     = (const float*)d_in[8];
    const float* b2     = (const float*)d_in[9];
    const float* gamma1 = (const float*)d_in[10];
    const float* beta1  = (const float*)d_in[11];
    const float* gamma2 = (const float*)d_in[12];
    const float* beta2  = (const float*)d_in[13];
    float* out = (float*)d_out;

    __half *p_x1, *p_qkv, *p_vT, *p_attn, *p_x2, *p_h, *p_wqkv, *p_wo, *p_w1, *p_w2;
    float *p_y;
    cudaGetSymbolAddress((void**)&p_x1,   g_x1);
    cudaGetSymbolAddress((void**)&p_qkv,  g_qkv);
    cudaGetSymbolAddress((void**)&p_vT,   g_vT);
    cudaGetSymbolAddress((void**)&p_attn, g_attn);
    cudaGetSymbolAddress((void**)&p_y,    g_y);
    cudaGetSymbolAddress((void**)&p_x2,   g_x2);
    cudaGetSymbolAddress((void**)&p_h,    g_h);
    cudaGetSymbolAddress((void**)&p_wqkv, g_wqkv);
    cudaGetSymbolAddress((void**)&p_wo,   g_wo);
    cudaGetSymbolAddress((void**)&p_w1,   g_w1);
    cudaGetSymbolAddress((void**)&p_w2,   g_w2);

    cudaFuncSetAttribute(gemm_f16_kernel<false, false, false, true>,
                         cudaFuncAttributeMaxDynamicSharedMemorySize, GEMM_SMEM);
    cudaFuncSetAttribute(gemm_f16_kernel<true, false, true, false>,
                         cudaFuncAttributeMaxDynamicSharedMemorySize, GEMM_SMEM);
    cudaFuncSetAttribute(gemm_f16_kernel<true, true, false, true>,
                         cudaFuncAttributeMaxDynamicSharedMemorySize, GEMM_SMEM);
    cudaFuncSetAttribute(attn_f16_kernel,
                         cudaFuncAttributeMaxDynamicSharedMemorySize, ATT_SMEM);

    dim3 tb(32, 8);

    // 0) fused weight prep
    prep_weights_kernel<<<12288, tb>>>(Wq, Wk, Wv, Wo, W1, W2);

    // 1) LN1 -> fp16
    {
        dim3 grid(Cc / 32, Bb), block(32, 32);
        ln_axis1_kernel<<<grid, block>>>(x, gamma1, beta1, p_x1);
    }

    // 2) fused QKV GEMM -> fp16 qkv
    {
        dim3 grid(QKV_N / 128, Mrows / 128);
        gemm_f16_kernel<false, false, false, true><<<grid, 256, GEMM_SMEM>>>(
            p_x1, p_wqkv, nullptr, nullptr, p_qkv, Mrows, QKV_N, Cc);
    }

    // 2b) V transpose
    transpose_v_kernel<<<dim3(Tt / 32, DHd / 32, Bb * Hh), tb>>>(p_qkv, p_vT);

    // 3) attention (BQ=128 per CTA, 256 threads)
    {
        dim3 grid(Tt / 128, Hh, Bb);
        attn_f16_kernel<<<grid, 256, ATT_SMEM>>>(p_qkv, p_vT, p_attn);
    }

    // 4) output projection + bias + residual -> y fp32
    {
        dim3 grid(Cc / 128, Mrows / 128);
        gemm_f16_kernel<true, false, true, false><<<grid, 256, GEMM_SMEM>>>(
            p_attn, p_wo, bo, x, p_y, Mrows, Cc, Cc);
    }

    // 5) LN2 -> fp16
    {
        dim3 grid(Cc / 32, Bb), block(32, 32);
        ln_axis1_kernel<<<grid, block>>>(p_y, gamma2, beta2, p_x2);
    }

    // 6) FFN1: h = relu(x2 @ W1 + b1) -> fp16
    {
        dim3 grid(FFN_N / 128, Mrows / 128);
        gemm_f16_kernel<true, true, false, true><<<grid, 256, GEMM_SMEM>>>(
            p_x2, p_w1, b1, nullptr, p_h, Mrows, FFN_N, Cc);
    }

    // 7) FFN2: out = y + h @ W2 + b2 -> fp32
    {
        dim3 grid(Cc / 128, Mrows / 128);
        gemm_f16_kernel<true, false, true, false><<<grid, 256, GEMM_SMEM>>>(
            p_h, p_w2, b2, p_y, out, Mrows, Cc, FFN_N);
    }
}

// round 12
// speedup vs baseline: 1.0211x; 1.0211x over previous
#include <cuda_runtime.h>
#include <cuda_fp16.h>
#include <math.h>
#include <stdint.h>

// Problem constants
#define Bb   2
#define Tt   2048
#define Cc   1024
#define Hh   16
#define DHd  64
#define Mrows (Bb * Tt)          // 4096
#define QKV_N (3 * Cc)           // 3072
#define FFN_N (4 * Cc)           // 4096
#define ATT_SCALE 0.03125f       // C^-0.5 = 1/32
#define LN_EPS 1e-5f

// ---------------------------------------------------------------------------
// Scratch (static device allocations; no cudaMalloc allowed)
// ---------------------------------------------------------------------------
__device__ __half g_x1  [Mrows * Cc];
__device__ __half g_qkv [Mrows * QKV_N];
__device__ __half g_attn[Mrows * Cc];
__device__ float  g_y   [Mrows * Cc];
__device__ __half g_x2  [Mrows * Cc];
__device__ __half g_h   [Mrows * FFN_N];
__device__ __half g_wqkv[QKV_N * Cc];
__device__ __half g_wo  [Cc * Cc];
__device__ __half g_w1  [FFN_N * Cc];
__device__ __half g_w2  [Cc * FFN_N];

// ---------------------------------------------------------------------------
// Helpers
// ---------------------------------------------------------------------------
__device__ __forceinline__ void cp_async16(void* smem, const void* gmem) {
    unsigned saddr = (unsigned)__cvta_generic_to_shared(smem);
    asm volatile("cp.async.cg.shared.global [%0], [%1], 16;\n"
                 :: "r"(saddr), "l"(gmem));
}
__device__ __forceinline__ void cp_async_commit() {
    asm volatile("cp.async.commit_group;\n" ::: "memory");
}
__device__ __forceinline__ void cp_async_wait0() {
    asm volatile("cp.async.wait_group 0;\n" ::: "memory");
}
__device__ __forceinline__ void cp_async_wait1() {
    asm volatile("cp.async.wait_group 1;\n" ::: "memory");
}

// fp16 mma: m16n8k16, fp32 accum
__device__ __forceinline__ void mma_f16(float c[4],
                                        const uint32_t a[4],
                                        const uint32_t b[2]) {
    asm volatile(
        "mma.sync.aligned.m16n8k16.row.col.f32.f16.f16.f32 "
        "{%0,%1,%2,%3}, {%4,%5,%6,%7}, {%8,%9}, {%0,%1,%2,%3};\n"
        : "+f"(c[0]), "+f"(c[1]), "+f"(c[2]), "+f"(c[3])
        : "r"(a[0]), "r"(a[1]), "r"(a[2]), "r"(a[3]),
          "r"(b[0]), "r"(b[1]));
}
__device__ __forceinline__ uint32_t pack_h2(float a, float b) {
    __half2 h = __floats2half2_rn(a, b);
    return *(uint32_t*)&h;
}
__device__ __forceinline__ void ldsm4(uint32_t r[4], uint32_t saddr) {
    asm volatile("ldmatrix.sync.aligned.m8n8.x4.shared.b16 {%0,%1,%2,%3}, [%4];"
                 : "=r"(r[0]), "=r"(r[1]), "=r"(r[2]), "=r"(r[3])
                 : "r"(saddr));
}
__device__ __forceinline__ void ldsm4t(uint32_t r[4], uint32_t saddr) {
    asm volatile("ldmatrix.sync.aligned.m8n8.x4.trans.shared.b16 {%0,%1,%2,%3}, [%4];"
                 : "=r"(r[0]), "=r"(r[1]), "=r"(r[2]), "=r"(r[3])
                 : "r"(saddr));
}

// ---------------------------------------------------------------------------
// Weight prep (separate kernels — Round-9 proven config)
// ---------------------------------------------------------------------------
__global__ __launch_bounds__(256)
void transpose_h_kernel(const float* __restrict__ in,
                        __half* __restrict__ out, int R, int Cn) {
    __shared__ float t[32][33];
    int c0 = blockIdx.x * 32, r0 = blockIdx.y * 32;
    int x = threadIdx.x, y = threadIdx.y;
#pragma unroll
    for (int i = 0; i < 32; i += 8)
        t[y + i][x] = in[(size_t)(r0 + y + i) * Cn + c0 + x];
    __syncthreads();
#pragma unroll
    for (int i = 0; i < 32; i += 8)
        out[(size_t)(c0 + y + i) * R + r0 + x] = __float2half(t[x][y + i]);
}

// pack Wq/Wk/Wv [H,C,DH] -> g_wqkv [3C][C] fp16 (transposed), ATT_SCALE in Wq
__global__ __launch_bounds__(256)
void pack_qkv_t_kernel(const float* __restrict__ Wq,
                       const float* __restrict__ Wk,
                       const float* __restrict__ Wv) {
    __shared__ float t[32][33];
    int c0 = blockIdx.x * 32, d0 = blockIdx.y * 32;
    int z = blockIdx.z;
    int sel = z >> 4, h = z & 15;
    const float* W = (sel == 0) ? Wq : (sel == 1) ? Wk : Wv;
    float scl = (sel == 0) ? ATT_SCALE : 1.0f;
    int x = threadIdx.x, y = threadIdx.y;
#pragma unroll
    for (int i = 0; i < 32; i += 8)
        t[y + i][x] = W[(size_t)(h * Cc + c0 + y + i) * DHd + d0 + x];
    __syncthreads();
#pragma unroll
    for (int i = 0; i < 32; i += 8)
        g_wqkv[(size_t)(sel * Cc + h * DHd + d0 + y + i) * Cc + c0 + x] =
            __float2half(t[x][y + i] * scl);
}

// ---------------------------------------------------------------------------
// LayerNorm over axis 1 (TIME), unbiased variance. fp16 out. 1024 thr/block.
// ---------------------------------------------------------------------------
__global__ __launch_bounds__(1024)
void ln_axis1_kernel(const float* __restrict__ x,
                     const float* __restrict__ gamma,
                     const float* __restrict__ beta,
                     __half* __restrict__ out) {
    int b  = blockIdx.y;
    int tx = threadIdx.x, ty = threadIdx.y;
    int c  = blockIdx.x * 32 + tx;
    const float* xp = x + (size_t)b * Tt * Cc + c;

    float s = 0.f, s2 = 0.f;
    for (int t = ty; t < Tt; t += 32) {
        float v = xp[(size_t)t * Cc];
        s += v; s2 += v * v;
    }
    __shared__ float ss[32][32], sq[32][32];
    __shared__ float smean[32], srstd[32];
    ss[ty][tx] = s; sq[ty][tx] = s2;
    __syncthreads();
    if (ty == 0) {
        float S = 0.f, S2 = 0.f;
#pragma unroll
        for (int k = 0; k < 32; k++) { S += ss[k][tx]; S2 += sq[k][tx]; }
        float mean = S / (float)Tt;
        float var  = (S2 - (float)Tt * mean * mean) / (float)(Tt - 1);
        smean[tx] = mean;
        srstd[tx] = rsqrtf(var + LN_EPS);
    }
    __syncthreads();
    float mean = smean[tx], rstd = srstd[tx];
    float g = gamma[c], be = beta[c];
    __half* op = out + (size_t)b * Tt * Cc + c;
    for (int t = ty; t < Tt; t += 32) {
        op[(size_t)t * Cc] = __float2half(g * (xp[(size_t)t * Cc] - mean) * rstd + be);
    }
}

// ---------------------------------------------------------------------------
// FP16 mma.sync GEMM, ldmatrix fragments, 3-stage cp.async (Round-9 PASS).
// ---------------------------------------------------------------------------
#define HSTR 40
#define TILE_H (128 * HSTR)
#define STG_H  (2 * TILE_H)
#define NSTG 3
#define GEMM_SMEM (NSTG * STG_H * 2)

template<bool BIAS, bool RELU, bool RES, bool OUTH>
__global__ __launch_bounds__(256, 2)
void gemm_f16_kernel(const __half* __restrict__ A,
                     const __half* __restrict__ Bt,
                     const float* __restrict__ bias,
                     const float* __restrict__ res,
                     void* __restrict__ CoutV,
                     int M, int N, int K) {
    extern __shared__ __half smh[];

    const int tid  = threadIdx.x;
    const int lane = tid & 31;
    const int warp = tid >> 5;
    const int wm   = warp >> 1;
    const int wn   = warp & 1;
    const int gid  = lane >> 2;
    const int tid4 = lane & 3;

    const int lrow = lane & 7;
    const int q    = lane >> 3;
    const int arow = (q & 1) * 8 + lrow;
    const int akof = (q >> 1) * 8;
    const int brow = (q >> 1) * 8 + lrow;
    const int bkof = (q & 1) * 8;

    const int row0 = blockIdx.y * 128;
    const int col0 = blockIdx.x * 128;
    const int nIter = K >> 5;

    const uint32_t sm_u = (uint32_t)__cvta_generic_to_shared(smh);

    float acc[2][8][4];
#pragma unroll
    for (int i = 0; i < 2; i++)
#pragma unroll
        for (int j = 0; j < 8; j++)
#pragma unroll
            for (int qq = 0; qq < 4; qq++) acc[i][j][qq] = 0.f;

    auto load_stage = [&](int s, int kc) {
        __half* as = smh + s * STG_H;
        __half* bs = as + TILE_H;
        const __half* ap = A  + (size_t)row0 * K + kc * 32;
        const __half* bp = Bt + (size_t)col0 * K + kc * 32;
#pragma unroll
        for (int qq = 0; qq < 2; qq++) {
            int id = tid + 256 * qq;
            int r = id >> 2, c8 = (id & 3) << 3;
            cp_async16(&as[r * HSTR + c8], ap + (size_t)r * K + c8);
        }
#pragma unroll
        for (int qq = 0; qq < 2; qq++) {
            int id = tid + 256 * qq;
            int r = id >> 2, c8 = (id & 3) << 3;
            cp_async16(&bs[r * HSTR + c8], bp + (size_t)r * K + c8);
        }
        cp_async_commit();
    };

    load_stage(0, 0);
    load_stage(1, 1);

    for (int it = 0; it < nIter; ++it) {
        cp_async_wait1();
        __syncthreads();

        if (it + 2 < nIter) load_stage((it + 2) % NSTG, it + 2);
        else                cp_async_commit();

        const int s = it % NSTG;
        const uint32_t as_u = sm_u + (s * STG_H) * 2;
        const uint32_t bs_u = as_u + TILE_H * 2;

#pragma unroll
        for (int ks = 0; ks < 2; ks++) {
            const int k0 = ks * 16;
            uint32_t af[2][4];
#pragma unroll
            for (int i = 0; i < 2; i++)
                ldsm4(af[i], as_u + ((wm * 32 + i * 16 + arow) * HSTR
                                     + k0 + akof) * 2);
            uint32_t bf[8][2];
#pragma unroll
            for (int jp = 0; jp < 4; jp++) {
                uint32_t t4[4];
                ldsm4(t4, bs_u + ((wn * 64 + 16 * jp + brow) * HSTR
                                  + k0 + bkof) * 2);
                bf[2 * jp][0]     = t4[0];
                bf[2 * jp][1]     = t4[1];
                bf[2 * jp + 1][0] = t4[2];
                bf[2 * jp + 1][1] = t4[3];
            }
#pragma unroll
            for (int i = 0; i < 2; i++)
#pragma unroll
                for (int j = 0; j < 8; j++)
                    mma_f16(acc[i][j], af[i], bf[j]);
        }
    }

    float*  Cf = (float*)CoutV;
    __half* Ch = (__half*)CoutV;
#pragma unroll
    for (int i = 0; i < 2; i++) {
#pragma unroll
        for (int hr = 0; hr < 2; hr++) {
            int r = row0 + wm * 32 + i * 16 + hr * 8 + gid;
#pragma unroll
            for (int j = 0; j < 8; j++) {
                int cI = col0 + wn * 64 + j * 8 + 2 * tid4;
                float v0 = acc[i][j][hr * 2];
                float v1 = acc[i][j][hr * 2 + 1];
                if (BIAS) {
                    float2 bi = *(const float2*)&bias[cI];
                    v0 += bi.x; v1 += bi.y;
                }
                if (RES) {
                    float2 rv = *(const float2*)&res[(size_t)r * N + cI];
                    v0 += rv.x; v1 += rv.y;
                }
                if (RELU) { v0 = fmaxf(v0, 0.f); v1 = fmaxf(v1, 0.f); }
                if (OUTH) {
                    *(__half2*)&Ch[(size_t)r * N + cI] = __floats2half2_rn(v0, v1);
                } else {
                    *(float2*)&Cf[(size_t)r * N + cI] = make_float2(v0, v1);
                }
            }
        }
    }
}

// ---------------------------------------------------------------------------
// Causal flash attention, fp16 mma + ldmatrix, register-direct P.
// Round-9 shape (BQ=64, 128 thr, occ 2). V consumed straight from qkv [s][d]
// via ldmatrix.trans (no separate V transpose kernel). Heavy CTAs first.
// ---------------------------------------------------------------------------
#define AST 72
#define ATT_SMEM ((64 + 128 + 128) * AST * 2)

__global__ __launch_bounds__(128, 2)
void attn_f16_kernel(const __half* __restrict__ qkv,
                     __half* __restrict__ outp) {
    extern __shared__ __half sha[];
    __half* Qs = sha;                   // [64][AST]
    __half* Ks = Qs + 64 * AST;         // [2][64][AST]  rows = s, cols = d
    __half* Vs = Ks + 2 * 64 * AST;     // [2][64][AST]  rows = s, cols = d

    const int qt = (int)gridDim.x - 1 - (int)blockIdx.x;   // heavy first
    const int h = blockIdx.y, b = blockIdx.z;
    const int t0 = qt * 64;
    const int tid  = threadIdx.x;
    const int lane = tid & 31;
    const int warp = tid >> 5;
    const int gid  = lane >> 2;
    const int tid4 = lane & 3;
    const unsigned FULL = 0xffffffffu;

    const int lrow = lane & 7;
    const int q    = lane >> 3;
    const int arow = (q & 1) * 8 + lrow;     // A-frag / non-trans mapping
    const int akof = (q >> 1) * 8;
    const int brow = (q >> 1) * 8 + lrow;    // B-frag non-trans (K)
    const int bkof = (q & 1) * 8;
    const int trow = (q & 1) * 8 + lrow;     // B-frag trans (V): k/n roles swapped
    const int tcol = (q >> 1) * 8;

    const uint32_t sm_u = (uint32_t)__cvta_generic_to_shared(sha);
    const uint32_t Qs_u = sm_u;
    const uint32_t Ks_u = sm_u + 64 * AST * 2;
    const uint32_t Vs_u = Ks_u + 2 * 64 * AST * 2;

    const __half* qb = qkv + (size_t)(b * Tt) * QKV_N + h * DHd;
    const __half* kb = qkv + (size_t)(b * Tt) * QKV_N + Cc + h * DHd;
    const __half* vb = qkv + (size_t)(b * Tt) * QKV_N + 2 * Cc + h * DHd;

#pragma unroll
    for (int qq = 0; qq < 4; qq++) {
        int id  = tid + 128 * qq;
        int row = id >> 3;
        int c8  = (id & 7) * 8;
        cp_async16(&Qs[row * AST + c8], qb + (size_t)(t0 + row) * QKV_N + c8);
        cp_async16(&Ks[row * AST + c8], kb + (size_t)row * QKV_N + c8);
        cp_async16(&Vs[row * AST + c8], vb + (size_t)row * QKV_N + c8);
    }
    cp_async_commit();
    cp_async_wait0();
    __syncthreads();

    uint32_t qa[4][4];
#pragma unroll
    for (int ks = 0; ks < 4; ks++)
        ldsm4(qa[ks], Qs_u + ((16 * warp + arow) * AST + 16 * ks + akof) * 2);

    float m0 = -1e30f, m1 = -1e30f, l0 = 0.f, l1 = 0.f;
    float o[8][4];
#pragma unroll
    for (int j = 0; j < 8; j++)
#pragma unroll
        for (int qq = 0; qq < 4; qq++) o[j][qq] = 0.f;

    const int nt = qt + 1;
    for (int it = 0; it < nt; ++it) {
        const int buf = it & 1;
        const uint32_t Kb_u = Ks_u + buf * 64 * AST * 2;
        const uint32_t Vb_u = Vs_u + buf * 64 * AST * 2;

        cp_async_wait0();
        __syncthreads();

        if (it + 1 < nt) {
            const int s0 = (it + 1) * 64;
            __half* Kn = Ks + (buf ^ 1) * 64 * AST;
            __half* Vn = Vs + (buf ^ 1) * 64 * AST;
#pragma unroll
            for (int qq = 0; qq < 4; qq++) {
                int id  = tid + 128 * qq;
                int row = id >> 3;
                int c8  = (id & 7) * 8;
                cp_async16(&Kn[row * AST + c8],
                           kb + (size_t)(s0 + row) * QKV_N + c8);
                cp_async16(&Vn[row * AST + c8],
                           vb + (size_t)(s0 + row) * QKV_N + c8);
            }
            cp_async_commit();
        }

        // ---- S = Q K^T ----
        float sc[8][4];
#pragma unroll
        for (int j = 0; j < 8; j++)
#pragma unroll
            for (int qq = 0; qq < 4; qq++) sc[j][qq] = 0.f;
#pragma unroll
        for (int ks = 0; ks < 4; ks++) {
            uint32_t kf[8][2];
#pragma unroll
            for (int jp = 0; jp < 4; jp++) {
                uint32_t t4[4];
                ldsm4(t4, Kb_u + ((16 * jp + brow) * AST + 16 * ks + bkof) * 2);
                kf[2 * jp][0]     = t4[0];
                kf[2 * jp][1]     = t4[1];
                kf[2 * jp + 1][0] = t4[2];
                kf[2 * jp + 1][1] = t4[3];
            }
#pragma unroll
            for (int j = 0; j < 8; j++)
                mma_f16(sc[j], qa[ks], kf[j]);
        }

        if (it == qt) {
            int r0 = 16 * warp + gid;
#pragma unroll
            for (int j = 0; j < 8; j++) {
                int c0 = 8 * j + 2 * tid4;
                if (c0     > r0)     sc[j][0] = -1e30f;
                if (c0 + 1 > r0)     sc[j][1] = -1e30f;
                if (c0     > r0 + 8) sc[j][2] = -1e30f;
                if (c0 + 1 > r0 + 8) sc[j][3] = -1e30f;
            }
        }

        // ---- online softmax ----
        float mx0 = -1e30f, mx1 = -1e30f;
#pragma unroll
        for (int j = 0; j < 8; j++) {
            mx0 = fmaxf(mx0, fmaxf(sc[j][0], sc[j][1]));
            mx1 = fmaxf(mx1, fmaxf(sc[j][2], sc[j][3]));
        }
        mx0 = fmaxf(mx0, __shfl_xor_sync(FULL, mx0, 1));
        mx0 = fmaxf(mx0, __shfl_xor_sync(FULL, mx0, 2));
        mx1 = fmaxf(mx1, __shfl_xor_sync(FULL, mx1, 1));
        mx1 = fmaxf(mx1, __shfl_xor_sync(FULL, mx1, 2));
        float mn0 = fmaxf(m0, mx0), mn1 = fmaxf(m1, mx1);
        float sum0 = 0.f, sum1 = 0.f;
#pragma unroll
        for (int j = 0; j < 8; j++) {
            sc[j][0] = __expf(sc[j][0] - mn0);
            sc[j][1] = __expf(sc[j][1] - mn0);
            sc[j][2] = __expf(sc[j][2] - mn1);
            sc[j][3] = __expf(sc[j][3] - mn1);
            sum0 += sc[j][0] + sc[j][1];
            sum1 += sc[j][2] + sc[j][3];
        }
        sum0 += __shfl_xor_sync(FULL, sum0, 1);
        sum0 += __shfl_xor_sync(FULL, sum0, 2);
        sum1 += __shfl_xor_sync(FULL, sum1, 1);
        sum1 += __shfl_xor_sync(FULL, sum1, 2);
        float c0 = __expf(m0 - mn0), c1 = __expf(m1 - mn1);
        l0 = l0 * c0 + sum0;
        l1 = l1 * c1 + sum1;
        m0 = mn0; m1 = mn1;
#pragma unroll
        for (int j = 0; j < 8; j++) {
            o[j][0] *= c0; o[j][1] *= c0;
            o[j][2] *= c1; o[j][3] *= c1;
        }

        // ---- O += P V : P from registers; V frags via ldmatrix.trans ----
#pragma unroll
        for (int ks = 0; ks < 4; ks++) {
            uint32_t pa[4];
            pa[0] = pack_h2(sc[2 * ks][0],     sc[2 * ks][1]);
            pa[1] = pack_h2(sc[2 * ks][2],     sc[2 * ks][3]);
            pa[2] = pack_h2(sc[2 * ks + 1][0], sc[2 * ks + 1][1]);
            pa[3] = pack_h2(sc[2 * ks + 1][2], sc[2 * ks + 1][3]);
            uint32_t vf[8][2];
#pragma unroll
            for (int jp = 0; jp < 4; jp++) {
                uint32_t t4[4];
                // V stored [s][d]; trans-load the (k=s, n=d) tile:
                // rows = s (16*ks + trow), cols = d (16*jp + tcol)
                ldsm4t(t4, Vb_u + ((16 * ks + trow) * AST + 16 * jp + tcol) * 2);
                vf[2 * jp][0]     = t4[0];
                vf[2 * jp][1]     = t4[1];
                vf[2 * jp + 1][0] = t4[2];
                vf[2 * jp + 1][1] = t4[3];
            }
#pragma unroll
            for (int j = 0; j < 8; j++)
                mma_f16(o[j], pa, vf[j]);
        }
    }

    float inv0 = 1.f / l0, inv1 = 1.f / l1;
    int r0 = t0 + 16 * warp + gid;
#pragma unroll
    for (int j = 0; j < 8; j++) {
        int cI = h * DHd + 8 * j + 2 * tid4;
        __half2 v0 = __floats2half2_rn(o[j][0] * inv0, o[j][1] * inv0);
        __half2 v1 = __floats2half2_rn(o[j][2] * inv1, o[j][3] * inv1);
        *(__half2*)&outp[(size_t)(b * Tt + r0) * Cc + cI]     = v0;
        *(__half2*)&outp[(size_t)(b * Tt + r0 + 8) * Cc + cI] = v1;
    }
}

// ---------------------------------------------------------------------------
// Launch
// ---------------------------------------------------------------------------
extern "C" void kernel_launch(void* const* d_in, const int* in_sizes, int n_in,
                              void* d_out, int out_size) {
    const float* x      = (const float*)d_in[0];
    const float* Wq     = (const float*)d_in[1];
    const float* Wk     = (const float*)d_in[2];
    const float* Wv     = (const float*)d_in[3];
    const float* Wo     = (const float*)d_in[4];
    const float* bo     = (const float*)d_in[5];
    const float* W1     = (const float*)d_in[6];
    const float* b1     = (const float*)d_in[7];
    const float* W2     = (const float*)d_in[8];
    const float* b2     = (const float*)d_in[9];
    const float* gamma1 = (const float*)d_in[10];
    const float* beta1  = (const float*)d_in[11];
    const float* gamma2 = (const float*)d_in[12];
    const float* beta2  = (const float*)d_in[13];
    float* out = (float*)d_out;

    __half *p_x1, *p_qkv, *p_attn, *p_x2, *p_h, *p_wqkv, *p_wo, *p_w1, *p_w2;
    float *p_y;
    cudaGetSymbolAddress((void**)&p_x1,   g_x1);
    cudaGetSymbolAddress((void**)&p_qkv,  g_qkv);
    cudaGetSymbolAddress((void**)&p_attn, g_attn);
    cudaGetSymbolAddress((void**)&p_y,    g_y);
    cudaGetSymbolAddress((void**)&p_x2,   g_x2);
    cudaGetSymbolAddress((void**)&p_h,    g_h);
    cudaGetSymbolAddress((void**)&p_wqkv, g_wqkv);
    cudaGetSymbolAddress((void**)&p_wo,   g_wo);
    cudaGetSymbolAddress((void**)&p_w1,   g_w1);
    cudaGetSymbolAddress((void**)&p_w2,   g_w2);

    cudaFuncSetAttribute(gemm_f16_kernel<false, false, false, true>,
                         cudaFuncAttributeMaxDynamicSharedMemorySize, GEMM_SMEM);
    cudaFuncSetAttribute(gemm_f16_kernel<true, false, true, false>,
                         cudaFuncAttributeMaxDynamicSharedMemorySize, GEMM_SMEM);
    cudaFuncSetAttribute(gemm_f16_kernel<true, true, false, true>,
                         cudaFuncAttributeMaxDynamicSharedMemorySize, GEMM_SMEM);
    cudaFuncSetAttribute(attn_f16_kernel,
                         cudaFuncAttributeMaxDynamicSharedMemorySize, ATT_SMEM);

    dim3 tb(32, 8);

    // 0) weight prep (separate kernels — Round-9 proven)
    pack_qkv_t_kernel<<<dim3(Cc / 32, DHd / 32, 48), tb>>>(Wq, Wk, Wv);
    transpose_h_kernel<<<dim3(Cc / 32, Cc / 32), tb>>>(Wo, p_wo, Cc, Cc);
    transpose_h_kernel<<<dim3(FFN_N / 32, Cc / 32), tb>>>(W1, p_w1, Cc, FFN_N);
    transpose_h_kernel<<<dim3(Cc / 32, FFN_N / 32), tb>>>(W2, p_w2, FFN_N, Cc);

    // 1) LN1 -> fp16
    {
        dim3 grid(Cc / 32, Bb), block(32, 32);
        ln_axis1_kernel<<<grid, block>>>(x, gamma1, beta1, p_x1);
    }

    // 2) fused QKV GEMM -> fp16 qkv
    {
        dim3 grid(QKV_N / 128, Mrows / 128);
        gemm_f16_kernel<false, false, false, true><<<grid, 256, GEMM_SMEM>>>(
            p_x1, p_wqkv, nullptr, nullptr, p_qkv, Mrows, QKV_N, Cc);
    }

    // 3) attention (V via ldmatrix.trans — no transpose kernel)
    {
        dim3 grid(Tt / 64, Hh, Bb);
        attn_f16_kernel<<<grid, 128, ATT_SMEM>>>(p_qkv, p_attn);
    }

    // 4) output projection + bias + residual -> y fp32
    {
        dim3 grid(Cc / 128, Mrows / 128);
        gemm_f16_kernel<true, false, true, false><<<grid, 256, GEMM_SMEM>>>(
            p_attn, p_wo, bo, x, p_y, Mrows, Cc, Cc);
    }

    // 5) LN2 -> fp16
    {
        dim3 grid(Cc / 32, Bb), block(32, 32);
        ln_axis1_kernel<<<grid, block>>>(p_y, gamma2, beta2, p_x2);
    }

    // 6) FFN1: h = relu(x2 @ W1 + b1) -> fp16
    {
        dim3 grid(FFN_N / 128, Mrows / 128);
        gemm_f16_kernel<true, true, false, true><<<grid, 256, GEMM_SMEM>>>(
            p_x2, p_w1, b1, nullptr, p_h, Mrows, FFN_N, Cc);
    }

    // 7) FFN2: out = y + h @ W2 + b2 -> fp32
    {
        dim3 grid(Cc / 128, Mrows / 128);
        gemm_f16_kernel<true, false, true, false><<<grid, 256, GEMM_SMEM>>>(
            p_h, p_w2, b2, p_y, out, Mrows, Cc, FFN_N);
    }
}

// round 13
// speedup vs baseline: 1.0275x; 1.0063x over previous
#include <cuda_runtime.h>
#include <cuda_fp16.h>
#include <math.h>
#include <stdint.h>

// Problem constants
#define Bb   2
#define Tt   2048
#define Cc   1024
#define Hh   16
#define DHd  64
#define Mrows (Bb * Tt)          // 4096
#define QKV_N (3 * Cc)           // 3072
#define FFN_N (4 * Cc)           // 4096
#define ATT_SCALE 0.03125f       // C^-0.5 = 1/32
#define LN_EPS 1e-5f

// ---------------------------------------------------------------------------
// Scratch (static device allocations; no cudaMalloc allowed)
// ---------------------------------------------------------------------------
__device__ __half g_x1  [Mrows * Cc];
__device__ __half g_qkv [Mrows * QKV_N];
__device__ __half g_attn[Mrows * Cc];
__device__ float  g_y   [Mrows * Cc];
__device__ __half g_x2  [Mrows * Cc];
__device__ __half g_h   [Mrows * FFN_N];
__device__ __half g_wqkv[QKV_N * Cc];
__device__ __half g_wo  [Cc * Cc];
__device__ __half g_w1  [FFN_N * Cc];
__device__ __half g_w2  [Cc * FFN_N];

// ---------------------------------------------------------------------------
// Helpers
// ---------------------------------------------------------------------------
__device__ __forceinline__ void cp_async16(void* smem, const void* gmem) {
    unsigned saddr = (unsigned)__cvta_generic_to_shared(smem);
    asm volatile("cp.async.cg.shared.global [%0], [%1], 16;\n"
                 :: "r"(saddr), "l"(gmem));
}
__device__ __forceinline__ void cp_async_commit() {
    asm volatile("cp.async.commit_group;\n" ::: "memory");
}
__device__ __forceinline__ void cp_async_wait0() {
    asm volatile("cp.async.wait_group 0;\n" ::: "memory");
}
__device__ __forceinline__ void cp_async_wait1() {
    asm volatile("cp.async.wait_group 1;\n" ::: "memory");
}

// fp16 mma: m16n8k16, fp32 accum
__device__ __forceinline__ void mma_f16(float c[4],
                                        const uint32_t a[4],
                                        const uint32_t b[2]) {
    asm volatile(
        "mma.sync.aligned.m16n8k16.row.col.f32.f16.f16.f32 "
        "{%0,%1,%2,%3}, {%4,%5,%6,%7}, {%8,%9}, {%0,%1,%2,%3};\n"
        : "+f"(c[0]), "+f"(c[1]), "+f"(c[2]), "+f"(c[3])
        : "r"(a[0]), "r"(a[1]), "r"(a[2]), "r"(a[3]),
          "r"(b[0]), "r"(b[1]));
}
__device__ __forceinline__ uint32_t pack_h2(float a, float b) {
    __half2 h = __floats2half2_rn(a, b);
    return *(uint32_t*)&h;
}
__device__ __forceinline__ void ldsm4(uint32_t r[4], uint32_t saddr) {
    asm volatile("ldmatrix.sync.aligned.m8n8.x4.shared.b16 {%0,%1,%2,%3}, [%4];"
                 : "=r"(r[0]), "=r"(r[1]), "=r"(r[2]), "=r"(r[3])
                 : "r"(saddr));
}
__device__ __forceinline__ void ldsm4t(uint32_t r[4], uint32_t saddr) {
    asm volatile("ldmatrix.sync.aligned.m8n8.x4.trans.shared.b16 {%0,%1,%2,%3}, [%4];"
                 : "=r"(r[0]), "=r"(r[1]), "=r"(r[2]), "=r"(r[3])
                 : "r"(saddr));
}

// ---------------------------------------------------------------------------
// Weight prep: 64x64-tile transposes, float4 reads, half2 writes.
// ---------------------------------------------------------------------------
// in [R][Cn] fp32 -> out [Cn][R] fp16 (optional scale)
__global__ __launch_bounds__(256)
void transpose64_kernel(const float* __restrict__ in,
                        __half* __restrict__ out, int R, int Cn) {
    __shared__ float t[64][65];
    const int c0 = blockIdx.x * 64, r0 = blockIdx.y * 64;
    const int tid = threadIdx.x;

    // read 64x64 floats, float4 per thread x4
#pragma unroll
    for (int k = 0; k < 4; k++) {
        int id  = tid + 256 * k;          // 0..1023
        int row = id >> 4;                // 0..63
        int c4  = (id & 15) << 2;         // 0..60
        float4 v = *(const float4*)(in + (size_t)(r0 + row) * Cn + c0 + c4);
        t[row][c4 + 0] = v.x; t[row][c4 + 1] = v.y;
        t[row][c4 + 2] = v.z; t[row][c4 + 3] = v.w;
    }
    __syncthreads();

    // write 64 output rows (c) x 32 half2 (r-pairs); warp rows coalesce 128B
    const int x = tid & 31;               // r-pair index
    const int y = tid >> 5;               // 0..7
#pragma unroll
    for (int i = 0; i < 8; i++) {
        int cy = y + 8 * i;               // output row (input col)
        __half2 v = __floats2half2_rn(t[2 * x][cy], t[2 * x + 1][cy]);
        *(__half2*)&out[(size_t)(c0 + cy) * R + r0 + 2 * x] = v;
    }
}

// pack Wq/Wk/Wv [H,C,DH] -> g_wqkv [3C][C] fp16 (transposed), ATT_SCALE in Wq.
// grid (C/64, 1, 48): z = sel*16+h; DH=64 = one tile.
__global__ __launch_bounds__(256)
void pack_qkv64_kernel(const float* __restrict__ Wq,
                       const float* __restrict__ Wk,
                       const float* __restrict__ Wv) {
    __shared__ float t[64][65];
    const int c0 = blockIdx.x * 64;
    const int z = blockIdx.z;
    const int sel = z >> 4, h = z & 15;
    const float* W = (sel == 0) ? Wq : (sel == 1) ? Wk : Wv;
    const float scl = (sel == 0) ? ATT_SCALE : 1.0f;
    const int tid = threadIdx.x;

    // read 64 c-rows x 64 d-cols
#pragma unroll
    for (int k = 0; k < 4; k++) {
        int id  = tid + 256 * k;
        int row = id >> 4;                // c offset 0..63
        int c4  = (id & 15) << 2;         // d offset
        float4 v = *(const float4*)(W + (size_t)(h * Cc + c0 + row) * DHd + c4);
        t[row][c4 + 0] = v.x * scl; t[row][c4 + 1] = v.y * scl;
        t[row][c4 + 2] = v.z * scl; t[row][c4 + 3] = v.w * scl;
    }
    __syncthreads();

    const int bn = sel * Cc + h * DHd;    // output row base
    const int x = tid & 31;
    const int y = tid >> 5;
#pragma unroll
    for (int i = 0; i < 8; i++) {
        int d = y + 8 * i;                // output row (d)
        __half2 v = __floats2half2_rn(t[2 * x][d], t[2 * x + 1][d]);
        *(__half2*)&g_wqkv[(size_t)(bn + d) * Cc + c0 + 2 * x] = v;
    }
}

// ---------------------------------------------------------------------------
// LayerNorm over axis 1 (TIME), unbiased variance. fp16 out. 1024 thr/block.
// ---------------------------------------------------------------------------
__global__ __launch_bounds__(1024)
void ln_axis1_kernel(const float* __restrict__ x,
                     const float* __restrict__ gamma,
                     const float* __restrict__ beta,
                     __half* __restrict__ out) {
    int b  = blockIdx.y;
    int tx = threadIdx.x, ty = threadIdx.y;
    int c  = blockIdx.x * 32 + tx;
    const float* xp = x + (size_t)b * Tt * Cc + c;

    float s = 0.f, s2 = 0.f;
    for (int t = ty; t < Tt; t += 32) {
        float v = xp[(size_t)t * Cc];
        s += v; s2 += v * v;
    }
    __shared__ float ss[32][32], sq[32][32];
    __shared__ float smean[32], srstd[32];
    ss[ty][tx] = s; sq[ty][tx] = s2;
    __syncthreads();
    if (ty == 0) {
        float S = 0.f, S2 = 0.f;
#pragma unroll
        for (int k = 0; k < 32; k++) { S += ss[k][tx]; S2 += sq[k][tx]; }
        float mean = S / (float)Tt;
        float var  = (S2 - (float)Tt * mean * mean) / (float)(Tt - 1);
        smean[tx] = mean;
        srstd[tx] = rsqrtf(var + LN_EPS);
    }
    __syncthreads();
    float mean = smean[tx], rstd = srstd[tx];
    float g = gamma[c], be = beta[c];
    __half* op = out + (size_t)b * Tt * Cc + c;
    for (int t = ty; t < Tt; t += 32) {
        op[(size_t)t * Cc] = __float2half(g * (xp[(size_t)t * Cc] - mean) * rstd + be);
    }
}

// ---------------------------------------------------------------------------
// FP16 mma.sync GEMM, ldmatrix fragments, 3-stage cp.async (Round-9 PASS).
// ---------------------------------------------------------------------------
#define HSTR 40
#define TILE_H (128 * HSTR)
#define STG_H  (2 * TILE_H)
#define NSTG 3
#define GEMM_SMEM (NSTG * STG_H * 2)

template<bool BIAS, bool RELU, bool RES, bool OUTH>
__global__ __launch_bounds__(256, 2)
void gemm_f16_kernel(const __half* __restrict__ A,
                     const __half* __restrict__ Bt,
                     const float* __restrict__ bias,
                     const float* __restrict__ res,
                     void* __restrict__ CoutV,
                     int M, int N, int K) {
    extern __shared__ __half smh[];

    const int tid  = threadIdx.x;
    const int lane = tid & 31;
    const int warp = tid >> 5;
    const int wm   = warp >> 1;
    const int wn   = warp & 1;
    const int gid  = lane >> 2;
    const int tid4 = lane & 3;

    const int lrow = lane & 7;
    const int q    = lane >> 3;
    const int arow = (q & 1) * 8 + lrow;
    const int akof = (q >> 1) * 8;
    const int brow = (q >> 1) * 8 + lrow;
    const int bkof = (q & 1) * 8;

    const int row0 = blockIdx.y * 128;
    const int col0 = blockIdx.x * 128;
    const int nIter = K >> 5;

    const uint32_t sm_u = (uint32_t)__cvta_generic_to_shared(smh);

    float acc[2][8][4];
#pragma unroll
    for (int i = 0; i < 2; i++)
#pragma unroll
        for (int j = 0; j < 8; j++)
#pragma unroll
            for (int qq = 0; qq < 4; qq++) acc[i][j][qq] = 0.f;

    auto load_stage = [&](int s, int kc) {
        __half* as = smh + s * STG_H;
        __half* bs = as + TILE_H;
        const __half* ap = A  + (size_t)row0 * K + kc * 32;
        const __half* bp = Bt + (size_t)col0 * K + kc * 32;
#pragma unroll
        for (int qq = 0; qq < 2; qq++) {
            int id = tid + 256 * qq;
            int r = id >> 2, c8 = (id & 3) << 3;
            cp_async16(&as[r * HSTR + c8], ap + (size_t)r * K + c8);
        }
#pragma unroll
        for (int qq = 0; qq < 2; qq++) {
            int id = tid + 256 * qq;
            int r = id >> 2, c8 = (id & 3) << 3;
            cp_async16(&bs[r * HSTR + c8], bp + (size_t)r * K + c8);
        }
        cp_async_commit();
    };

    load_stage(0, 0);
    load_stage(1, 1);

    for (int it = 0; it < nIter; ++it) {
        cp_async_wait1();
        __syncthreads();

        if (it + 2 < nIter) load_stage((it + 2) % NSTG, it + 2);
        else                cp_async_commit();

        const int s = it % NSTG;
        const uint32_t as_u = sm_u + (s * STG_H) * 2;
        const uint32_t bs_u = as_u + TILE_H * 2;

#pragma unroll
        for (int ks = 0; ks < 2; ks++) {
            const int k0 = ks * 16;
            uint32_t af[2][4];
#pragma unroll
            for (int i = 0; i < 2; i++)
                ldsm4(af[i], as_u + ((wm * 32 + i * 16 + arow) * HSTR
                                     + k0 + akof) * 2);
            uint32_t bf[8][2];
#pragma unroll
            for (int jp = 0; jp < 4; jp++) {
                uint32_t t4[4];
                ldsm4(t4, bs_u + ((wn * 64 + 16 * jp + brow) * HSTR
                                  + k0 + bkof) * 2);
                bf[2 * jp][0]     = t4[0];
                bf[2 * jp][1]     = t4[1];
                bf[2 * jp + 1][0] = t4[2];
                bf[2 * jp + 1][1] = t4[3];
            }
#pragma unroll
            for (int i = 0; i < 2; i++)
#pragma unroll
                for (int j = 0; j < 8; j++)
                    mma_f16(acc[i][j], af[i], bf[j]);
        }
    }

    float*  Cf = (float*)CoutV;
    __half* Ch = (__half*)CoutV;
#pragma unroll
    for (int i = 0; i < 2; i++) {
#pragma unroll
        for (int hr = 0; hr < 2; hr++) {
            int r = row0 + wm * 32 + i * 16 + hr * 8 + gid;
#pragma unroll
            for (int j = 0; j < 8; j++) {
                int cI = col0 + wn * 64 + j * 8 + 2 * tid4;
                float v0 = acc[i][j][hr * 2];
                float v1 = acc[i][j][hr * 2 + 1];
                if (BIAS) {
                    float2 bi = *(const float2*)&bias[cI];
                    v0 += bi.x; v1 += bi.y;
                }
                if (RES) {
                    float2 rv = *(const float2*)&res[(size_t)r * N + cI];
                    v0 += rv.x; v1 += rv.y;
                }
                if (RELU) { v0 = fmaxf(v0, 0.f); v1 = fmaxf(v1, 0.f); }
                if (OUTH) {
                    *(__half2*)&Ch[(size_t)r * N + cI] = __floats2half2_rn(v0, v1);
                } else {
                    *(float2*)&Cf[(size_t)r * N + cI] = make_float2(v0, v1);
                }
            }
        }
    }
}

// ---------------------------------------------------------------------------
// Causal flash attention (Round-12 PASS): fp16 mma + ldmatrix, register-
// direct P, V via ldmatrix.trans straight from qkv. Heavy CTAs first.
// ---------------------------------------------------------------------------
#define AST 72
#define ATT_SMEM ((64 + 128 + 128) * AST * 2)

__global__ __launch_bounds__(128, 2)
void attn_f16_kernel(const __half* __restrict__ qkv,
                     __half* __restrict__ outp) {
    extern __shared__ __half sha[];
    __half* Qs = sha;                   // [64][AST]
    __half* Ks = Qs + 64 * AST;         // [2][64][AST]  rows = s, cols = d
    __half* Vs = Ks + 2 * 64 * AST;     // [2][64][AST]  rows = s, cols = d

    const int qt = (int)gridDim.x - 1 - (int)blockIdx.x;   // heavy first
    const int h = blockIdx.y, b = blockIdx.z;
    const int t0 = qt * 64;
    const int tid  = threadIdx.x;
    const int lane = tid & 31;
    const int warp = tid >> 5;
    const int gid  = lane >> 2;
    const int tid4 = lane & 3;
    const unsigned FULL = 0xffffffffu;

    const int lrow = lane & 7;
    const int q    = lane >> 3;
    const int arow = (q & 1) * 8 + lrow;
    const int akof = (q >> 1) * 8;
    const int brow = (q >> 1) * 8 + lrow;
    const int bkof = (q & 1) * 8;
    const int trow = (q & 1) * 8 + lrow;     // trans (V): k/n roles swapped
    const int tcol = (q >> 1) * 8;

    const uint32_t sm_u = (uint32_t)__cvta_generic_to_shared(sha);
    const uint32_t Qs_u = sm_u;
    const uint32_t Ks_u = sm_u + 64 * AST * 2;
    const uint32_t Vs_u = Ks_u + 2 * 64 * AST * 2;

    const __half* qb = qkv + (size_t)(b * Tt) * QKV_N + h * DHd;
    const __half* kb = qkv + (size_t)(b * Tt) * QKV_N + Cc + h * DHd;
    const __half* vb = qkv + (size_t)(b * Tt) * QKV_N + 2 * Cc + h * DHd;

#pragma unroll
    for (int qq = 0; qq < 4; qq++) {
        int id  = tid + 128 * qq;
        int row = id >> 3;
        int c8  = (id & 7) * 8;
        cp_async16(&Qs[row * AST + c8], qb + (size_t)(t0 + row) * QKV_N + c8);
        cp_async16(&Ks[row * AST + c8], kb + (size_t)row * QKV_N + c8);
        cp_async16(&Vs[row * AST + c8], vb + (size_t)row * QKV_N + c8);
    }
    cp_async_commit();
    cp_async_wait0();
    __syncthreads();

    uint32_t qa[4][4];
#pragma unroll
    for (int ks = 0; ks < 4; ks++)
        ldsm4(qa[ks], Qs_u + ((16 * warp + arow) * AST + 16 * ks + akof) * 2);

    float m0 = -1e30f, m1 = -1e30f, l0 = 0.f, l1 = 0.f;
    float o[8][4];
#pragma unroll
    for (int j = 0; j < 8; j++)
#pragma unroll
        for (int qq = 0; qq < 4; qq++) o[j][qq] = 0.f;

    const int nt = qt + 1;
    for (int it = 0; it < nt; ++it) {
        const int buf = it & 1;
        const uint32_t Kb_u = Ks_u + buf * 64 * AST * 2;
        const uint32_t Vb_u = Vs_u + buf * 64 * AST * 2;

        cp_async_wait0();
        __syncthreads();

        if (it + 1 < nt) {
            const int s0 = (it + 1) * 64;
            __half* Kn = Ks + (buf ^ 1) * 64 * AST;
            __half* Vn = Vs + (buf ^ 1) * 64 * AST;
#pragma unroll
            for (int qq = 0; qq < 4; qq++) {
                int id  = tid + 128 * qq;
                int row = id >> 3;
                int c8  = (id & 7) * 8;
                cp_async16(&Kn[row * AST + c8],
                           kb + (size_t)(s0 + row) * QKV_N + c8);
                cp_async16(&Vn[row * AST + c8],
                           vb + (size_t)(s0 + row) * QKV_N + c8);
            }
            cp_async_commit();
        }

        // ---- S = Q K^T ----
        float sc[8][4];
#pragma unroll
        for (int j = 0; j < 8; j++)
#pragma unroll
            for (int qq = 0; qq < 4; qq++) sc[j][qq] = 0.f;
#pragma unroll
        for (int ks = 0; ks < 4; ks++) {
            uint32_t kf[8][2];
#pragma unroll
            for (int jp = 0; jp < 4; jp++) {
                uint32_t t4[4];
                ldsm4(t4, Kb_u + ((16 * jp + brow) * AST + 16 * ks + bkof) * 2);
                kf[2 * jp][0]     = t4[0];
                kf[2 * jp][1]     = t4[1];
                kf[2 * jp + 1][0] = t4[2];
                kf[2 * jp + 1][1] = t4[3];
            }
#pragma unroll
            for (int j = 0; j < 8; j++)
                mma_f16(sc[j], qa[ks], kf[j]);
        }

        if (it == qt) {
            int r0 = 16 * warp + gid;
#pragma unroll
            for (int j = 0; j < 8; j++) {
                int c0 = 8 * j + 2 * tid4;
                if (c0     > r0)     sc[j][0] = -1e30f;
                if (c0 + 1 > r0)     sc[j][1] = -1e30f;
                if (c0     > r0 + 8) sc[j][2] = -1e30f;
                if (c0 + 1 > r0 + 8) sc[j][3] = -1e30f;
            }
        }

        // ---- online softmax ----
        float mx0 = -1e30f, mx1 = -1e30f;
#pragma unroll
        for (int j = 0; j < 8; j++) {
            mx0 = fmaxf(mx0, fmaxf(sc[j][0], sc[j][1]));
            mx1 = fmaxf(mx1, fmaxf(sc[j][2], sc[j][3]));
        }
        mx0 = fmaxf(mx0, __shfl_xor_sync(FULL, mx0, 1));
        mx0 = fmaxf(mx0, __shfl_xor_sync(FULL, mx0, 2));
        mx1 = fmaxf(mx1, __shfl_xor_sync(FULL, mx1, 1));
        mx1 = fmaxf(mx1, __shfl_xor_sync(FULL, mx1, 2));
        float mn0 = fmaxf(m0, mx0), mn1 = fmaxf(m1, mx1);
        float sum0 = 0.f, sum1 = 0.f;
#pragma unroll
        for (int j = 0; j < 8; j++) {
            sc[j][0] = __expf(sc[j][0] - mn0);
            sc[j][1] = __expf(sc[j][1] - mn0);
            sc[j][2] = __expf(sc[j][2] - mn1);
            sc[j][3] = __expf(sc[j][3] - mn1);
            sum0 += sc[j][0] + sc[j][1];
            sum1 += sc[j][2] + sc[j][3];
        }
        sum0 += __shfl_xor_sync(FULL, sum0, 1);
        sum0 += __shfl_xor_sync(FULL, sum0, 2);
        sum1 += __shfl_xor_sync(FULL, sum1, 1);
        sum1 += __shfl_xor_sync(FULL, sum1, 2);
        float c0 = __expf(m0 - mn0), c1 = __expf(m1 - mn1);
        l0 = l0 * c0 + sum0;
        l1 = l1 * c1 + sum1;
        m0 = mn0; m1 = mn1;
#pragma unroll
        for (int j = 0; j < 8; j++) {
            o[j][0] *= c0; o[j][1] *= c0;
            o[j][2] *= c1; o[j][3] *= c1;
        }

        // ---- O += P V : P from registers; V frags via ldmatrix.trans ----
#pragma unroll
        for (int ks = 0; ks < 4; ks++) {
            uint32_t pa[4];
            pa[0] = pack_h2(sc[2 * ks][0],     sc[2 * ks][1]);
            pa[1] = pack_h2(sc[2 * ks][2],     sc[2 * ks][3]);
            pa[2] = pack_h2(sc[2 * ks + 1][0], sc[2 * ks + 1][1]);
            pa[3] = pack_h2(sc[2 * ks + 1][2], sc[2 * ks + 1][3]);
            uint32_t vf[8][2];
#pragma unroll
            for (int jp = 0; jp < 4; jp++) {
                uint32_t t4[4];
                ldsm4t(t4, Vb_u + ((16 * ks + trow) * AST + 16 * jp + tcol) * 2);
                vf[2 * jp][0]     = t4[0];
                vf[2 * jp][1]     = t4[1];
                vf[2 * jp + 1][0] = t4[2];
                vf[2 * jp + 1][1] = t4[3];
            }
#pragma unroll
            for (int j = 0; j < 8; j++)
                mma_f16(o[j], pa, vf[j]);
        }
    }

    float inv0 = 1.f / l0, inv1 = 1.f / l1;
    int r0 = t0 + 16 * warp + gid;
#pragma unroll
    for (int j = 0; j < 8; j++) {
        int cI = h * DHd + 8 * j + 2 * tid4;
        __half2 v0 = __floats2half2_rn(o[j][0] * inv0, o[j][1] * inv0);
        __half2 v1 = __floats2half2_rn(o[j][2] * inv1, o[j][3] * inv1);
        *(__half2*)&outp[(size_t)(b * Tt + r0) * Cc + cI]     = v0;
        *(__half2*)&outp[(size_t)(b * Tt + r0 + 8) * Cc + cI] = v1;
    }
}

// ---------------------------------------------------------------------------
// Launch
// ---------------------------------------------------------------------------
extern "C" void kernel_launch(void* const* d_in, const int* in_sizes, int n_in,
                              void* d_out, int out_size) {
    const float* x      = (const float*)d_in[0];
    const float* Wq     = (const float*)d_in[1];
    const float* Wk     = (const float*)d_in[2];
    const float* Wv     = (const float*)d_in[3];
    const float* Wo     = (const float*)d_in[4];
    const float* bo     = (const float*)d_in[5];
    const float* W1     = (const float*)d_in[6];
    const float* b1     = (const float*)d_in[7];
    const float* W2     = (const float*)d_in[8];
    const float* b2     = (const float*)d_in[9];
    const float* gamma1 = (const float*)d_in[10];
    const float* beta1  = (const float*)d_in[11];
    const float* gamma2 = (const float*)d_in[12];
    const float* beta2  = (const float*)d_in[13];
    float* out = (float*)d_out;

    __half *p_x1, *p_qkv, *p_attn, *p_x2, *p_h, *p_wqkv, *p_wo, *p_w1, *p_w2;
    float *p_y;
    cudaGetSymbolAddress((void**)&p_x1,   g_x1);
    cudaGetSymbolAddress((void**)&p_qkv,  g_qkv);
    cudaGetSymbolAddress((void**)&p_attn, g_attn);
    cudaGetSymbolAddress((void**)&p_y,    g_y);
    cudaGetSymbolAddress((void**)&p_x2,   g_x2);
    cudaGetSymbolAddress((void**)&p_h,    g_h);
    cudaGetSymbolAddress((void**)&p_wqkv, g_wqkv);
    cudaGetSymbolAddress((void**)&p_wo,   g_wo);
    cudaGetSymbolAddress((void**)&p_w1,   g_w1);
    cudaGetSymbolAddress((void**)&p_w2,   g_w2);

    cudaFuncSetAttribute(gemm_f16_kernel<false, false, false, true>,
                         cudaFuncAttributeMaxDynamicSharedMemorySize, GEMM_SMEM);
    cudaFuncSetAttribute(gemm_f16_kernel<true, false, true, false>,
                         cudaFuncAttributeMaxDynamicSharedMemorySize, GEMM_SMEM);
    cudaFuncSetAttribute(gemm_f16_kernel<true, true, false, true>,
                         cudaFuncAttributeMaxDynamicSharedMemorySize, GEMM_SMEM);
    cudaFuncSetAttribute(attn_f16_kernel,
                         cudaFuncAttributeMaxDynamicSharedMemorySize, ATT_SMEM);

    // 0) weight prep (64x64 tiles, vectorized)
    pack_qkv64_kernel<<<dim3(Cc / 64, 1, 48), 256>>>(Wq, Wk, Wv);
    transpose64_kernel<<<dim3(Cc / 64, Cc / 64), 256>>>(Wo, p_wo, Cc, Cc);
    transpose64_kernel<<<dim3(FFN_N / 64, Cc / 64), 256>>>(W1, p_w1, Cc, FFN_N);
    transpose64_kernel<<<dim3(Cc / 64, FFN_N / 64), 256>>>(W2, p_w2, FFN_N, Cc);

    // 1) LN1 -> fp16
    {
        dim3 grid(Cc / 32, Bb), block(32, 32);
        ln_axis1_kernel<<<grid, block>>>(x, gamma1, beta1, p_x1);
    }

    // 2) fused QKV GEMM -> fp16 qkv
    {
        dim3 grid(QKV_N / 128, Mrows / 128);
        gemm_f16_kernel<false, false, false, true><<<grid, 256, GEMM_SMEM>>>(
            p_x1, p_wqkv, nullptr, nullptr, p_qkv, Mrows, QKV_N, Cc);
    }

    // 3) attention
    {
        dim3 grid(Tt / 64, Hh, Bb);
        attn_f16_kernel<<<grid, 128, ATT_SMEM>>>(p_qkv, p_attn);
    }

    // 4) output projection + bias + residual -> y fp32
    {
        dim3 grid(Cc / 128, Mrows / 128);
        gemm_f16_kernel<true, false, true, false><<<grid, 256, GEMM_SMEM>>>(
            p_attn, p_wo, bo, x, p_y, Mrows, Cc, Cc);
    }

    // 5) LN2 -> fp16
    {
        dim3 grid(Cc / 32, Bb), block(32, 32);
        ln_axis1_kernel<<<grid, block>>>(p_y, gamma2, beta2, p_x2);
    }

    // 6) FFN1: h = relu(x2 @ W1 + b1) -> fp16
    {
        dim3 grid(FFN_N / 128, Mrows / 128);
        gemm_f16_kernel<true, true, false, true><<<grid, 256, GEMM_SMEM>>>(
            p_x2, p_w1, b1, nullptr, p_h, Mrows, FFN_N, Cc);
    }

    // 7) FFN2: out = y + h @ W2 + b2 -> fp32
    {
        dim3 grid(Cc / 128, Mrows / 128);
        gemm_f16_kernel<true, false, true, false><<<grid, 256, GEMM_SMEM>>>(
            p_h, p_w2, b2, p_y, out, Mrows, Cc, FFN_N);
    }
}

// round 14
// speedup vs baseline: 1.0483x; 1.0202x over previous
#include <cuda_runtime.h>
#include <cuda_fp16.h>
#include <math.h>
#include <stdint.h>

// Problem constants
#define Bb   2
#define Tt   2048
#define Cc   1024
#define Hh   16
#define DHd  64
#define Mrows (Bb * Tt)          // 4096
#define QKV_N (3 * Cc)           // 3072
#define FFN_N (4 * Cc)           // 4096
#define ATT_SCALE 0.03125f       // C^-0.5 = 1/32
#define LN_EPS 1e-5f

// ---------------------------------------------------------------------------
// Scratch (static device allocations; no cudaMalloc allowed)
// ---------------------------------------------------------------------------
__device__ __half g_x1  [Mrows * Cc];
__device__ __half g_qkv [Mrows * QKV_N];
__device__ __half g_attn[Mrows * Cc];
__device__ float  g_y   [Mrows * Cc];
__device__ __half g_x2  [Mrows * Cc];
__device__ __half g_h   [Mrows * FFN_N];
__device__ __half g_wqkv[Cc * QKV_N];     // [C][3C]  (K-major, n = sel*1024+h*64+d)
__device__ __half g_wo  [Cc * Cc];        // [K][N]
__device__ __half g_w1  [Cc * FFN_N];     // [K][N]
__device__ __half g_w2  [FFN_N * Cc];     // [K][N]

// ---------------------------------------------------------------------------
// Helpers
// ---------------------------------------------------------------------------
__device__ __forceinline__ void cp_async16(void* smem, const void* gmem) {
    unsigned saddr = (unsigned)__cvta_generic_to_shared(smem);
    asm volatile("cp.async.cg.shared.global [%0], [%1], 16;\n"
                 :: "r"(saddr), "l"(gmem));
}
__device__ __forceinline__ void cp_async_commit() {
    asm volatile("cp.async.commit_group;\n" ::: "memory");
}
__device__ __forceinline__ void cp_async_wait0() {
    asm volatile("cp.async.wait_group 0;\n" ::: "memory");
}
__device__ __forceinline__ void cp_async_wait1() {
    asm volatile("cp.async.wait_group 1;\n" ::: "memory");
}

// fp16 mma: m16n8k16, fp32 accum
__device__ __forceinline__ void mma_f16(float c[4],
                                        const uint32_t a[4],
                                        const uint32_t b[2]) {
    asm volatile(
        "mma.sync.aligned.m16n8k16.row.col.f32.f16.f16.f32 "
        "{%0,%1,%2,%3}, {%4,%5,%6,%7}, {%8,%9}, {%0,%1,%2,%3};\n"
        : "+f"(c[0]), "+f"(c[1]), "+f"(c[2]), "+f"(c[3])
        : "r"(a[0]), "r"(a[1]), "r"(a[2]), "r"(a[3]),
          "r"(b[0]), "r"(b[1]));
}
__device__ __forceinline__ uint32_t pack_h2(float a, float b) {
    __half2 h = __floats2half2_rn(a, b);
    return *(uint32_t*)&h;
}
__device__ __forceinline__ void ldsm4(uint32_t r[4], uint32_t saddr) {
    asm volatile("ldmatrix.sync.aligned.m8n8.x4.shared.b16 {%0,%1,%2,%3}, [%4];"
                 : "=r"(r[0]), "=r"(r[1]), "=r"(r[2]), "=r"(r[3])
                 : "r"(saddr));
}
__device__ __forceinline__ void ldsm4t(uint32_t r[4], uint32_t saddr) {
    asm volatile("ldmatrix.sync.aligned.m8n8.x4.trans.shared.b16 {%0,%1,%2,%3}, [%4];"
                 : "=r"(r[0]), "=r"(r[1]), "=r"(r[2]), "=r"(r[3])
                 : "r"(saddr));
}

// ---------------------------------------------------------------------------
// Weight prep — NO transposes. Pure fp32->fp16 streaming copies.
// ---------------------------------------------------------------------------
__global__ __launch_bounds__(256)
void round_h_kernel(const float* __restrict__ in,
                    __half* __restrict__ out, int n4) {
    int i = (blockIdx.x * 256 + threadIdx.x);
    if (i >= n4) return;
    float4 v = *(const float4*)(in + 4 * (size_t)i);
    __half2 a = __floats2half2_rn(v.x, v.y);
    __half2 b = __floats2half2_rn(v.z, v.w);
    *(__half2*)(out + 4 * (size_t)i)     = a;
    *(__half2*)(out + 4 * (size_t)i + 2) = b;
}

// Wq/Wk/Wv [H,C,DH] -> g_wqkv [C][3C], col n = sel*1024 + h*64 + d.
// Both read and write contiguous over d — no smem needed. ATT_SCALE in Wq.
__global__ __launch_bounds__(256)
void pack_qkv_kn_kernel(const float* __restrict__ Wq,
                        const float* __restrict__ Wk,
                        const float* __restrict__ Wv) {
    int gid = blockIdx.x * 256 + threadIdx.x;       // 0 .. 3*1024*1024/4 - 1
    int e   = gid * 4;
    int d    = e & 63;
    int rest = e >> 6;                              // c*48 + sel*16 + h
    int c   = rest / 48;
    int r2  = rest - c * 48;
    int sel = r2 >> 4;
    int h   = r2 & 15;
    const float* W = (sel == 0) ? Wq : (sel == 1) ? Wk : Wv;
    float scl = (sel == 0) ? ATT_SCALE : 1.0f;
    float4 v = *(const float4*)(W + ((size_t)(h * Cc + c)) * DHd + d);
    __half2 a = __floats2half2_rn(v.x * scl, v.y * scl);
    __half2 b = __floats2half2_rn(v.z * scl, v.w * scl);
    __half* op = g_wqkv + (size_t)c * QKV_N + sel * Cc + h * DHd + d;
    *(__half2*)op       = a;
    *(__half2*)(op + 2) = b;
}

// ---------------------------------------------------------------------------
// LayerNorm over axis 1 (TIME), unbiased variance. fp16 out. 1024 thr/block.
// ---------------------------------------------------------------------------
__global__ __launch_bounds__(1024)
void ln_axis1_kernel(const float* __restrict__ x,
                     const float* __restrict__ gamma,
                     const float* __restrict__ beta,
                     __half* __restrict__ out) {
    int b  = blockIdx.y;
    int tx = threadIdx.x, ty = threadIdx.y;
    int c  = blockIdx.x * 32 + tx;
    const float* xp = x + (size_t)b * Tt * Cc + c;

    float s = 0.f, s2 = 0.f;
    for (int t = ty; t < Tt; t += 32) {
        float v = xp[(size_t)t * Cc];
        s += v; s2 += v * v;
    }
    __shared__ float ss[32][32], sq[32][32];
    __shared__ float smean[32], srstd[32];
    ss[ty][tx] = s; sq[ty][tx] = s2;
    __syncthreads();
    if (ty == 0) {
        float S = 0.f, S2 = 0.f;
#pragma unroll
        for (int k = 0; k < 32; k++) { S += ss[k][tx]; S2 += sq[k][tx]; }
        float mean = S / (float)Tt;
        float var  = (S2 - (float)Tt * mean * mean) / (float)(Tt - 1);
        smean[tx] = mean;
        srstd[tx] = rsqrtf(var + LN_EPS);
    }
    __syncthreads();
    float mean = smean[tx], rstd = srstd[tx];
    float g = gamma[c], be = beta[c];
    __half* op = out + (size_t)b * Tt * Cc + c;
    for (int t = ty; t < Tt; t += 32) {
        op[(size_t)t * Cc] = __float2half(g * (xp[(size_t)t * Cc] - mean) * rstd + be);
    }
}

// ---------------------------------------------------------------------------
// FP16 mma.sync GEMM: C[M,N] = epilogue(A[M,K] @ B[K,N]).
// A [M][K] fp16; B [K][N] fp16 (natural layout; frags via ldmatrix.trans).
// CTA 128x128, BK=32, 256 thr = 8 warps (4m x 2n), 3-stage cp.async, 2 CTAs/SM.
// ---------------------------------------------------------------------------
#define HSTR 40
#define BSTR 136
#define A_TILE_H (128 * HSTR)               // 5120 halves
#define B_TILE_H (32 * BSTR)                // 4352 halves
#define STG_H  (A_TILE_H + B_TILE_H)        // 9472 halves
#define NSTG 3
#define GEMM_SMEM (NSTG * STG_H * 2)        // 56832 B

template<bool BIAS, bool RELU, bool RES, bool OUTH>
__global__ __launch_bounds__(256, 2)
void gemm_f16_kernel(const __half* __restrict__ A,
                     const __half* __restrict__ Bm,
                     const float* __restrict__ bias,
                     const float* __restrict__ res,
                     void* __restrict__ CoutV,
                     int M, int N, int K) {
    extern __shared__ __half smh[];

    const int tid  = threadIdx.x;
    const int lane = tid & 31;
    const int warp = tid >> 5;
    const int wm   = warp >> 1;
    const int wn   = warp & 1;
    const int gid  = lane >> 2;
    const int tid4 = lane & 3;

    const int lrow = lane & 7;
    const int q    = lane >> 3;
    const int arow = (q & 1) * 8 + lrow;     // A non-trans mapping
    const int akof = (q >> 1) * 8;
    const int trow = (q & 1) * 8 + lrow;     // B trans mapping (k rows)
    const int tcol = (q >> 1) * 8;           // n offset 0/8

    const int row0 = blockIdx.y * 128;
    const int col0 = blockIdx.x * 128;
    const int nIter = K >> 5;

    const uint32_t sm_u = (uint32_t)__cvta_generic_to_shared(smh);

    float acc[2][8][4];
#pragma unroll
    for (int i = 0; i < 2; i++)
#pragma unroll
        for (int j = 0; j < 8; j++)
#pragma unroll
            for (int qq = 0; qq < 4; qq++) acc[i][j][qq] = 0.f;

    auto load_stage = [&](int s, int kc) {
        __half* as = smh + s * STG_H;
        __half* bs = as + A_TILE_H;
        const __half* ap = A  + (size_t)row0 * K + kc * 32;
        const __half* bp = Bm + (size_t)(kc * 32) * N + col0;
        // A tile: 128 rows x 32 k
#pragma unroll
        for (int qq = 0; qq < 2; qq++) {
            int id = tid + 256 * qq;
            int r = id >> 2, c8 = (id & 3) << 3;
            cp_async16(&as[r * HSTR + c8], ap + (size_t)r * K + c8);
        }
        // B tile: 32 k-rows x 128 n
#pragma unroll
        for (int qq = 0; qq < 2; qq++) {
            int id = tid + 256 * qq;
            int r = id >> 4, c8 = (id & 15) << 3;
            cp_async16(&bs[r * BSTR + c8], bp + (size_t)r * N + c8);
        }
        cp_async_commit();
    };

    load_stage(0, 0);
    load_stage(1, 1);

    for (int it = 0; it < nIter; ++it) {
        cp_async_wait1();
        __syncthreads();

        if (it + 2 < nIter) load_stage((it + 2) % NSTG, it + 2);
        else                cp_async_commit();

        const int s = it % NSTG;
        const uint32_t as_u = sm_u + (s * STG_H) * 2;
        const uint32_t bs_u = as_u + A_TILE_H * 2;

#pragma unroll
        for (int ks = 0; ks < 2; ks++) {
            const int k0 = ks * 16;
            uint32_t af[2][4];
#pragma unroll
            for (int i = 0; i < 2; i++)
                ldsm4(af[i], as_u + ((wm * 32 + i * 16 + arow) * HSTR
                                     + k0 + akof) * 2);
            uint32_t bf[8][2];
#pragma unroll
            for (int jp = 0; jp < 4; jp++) {
                uint32_t t4[4];
                ldsm4t(t4, bs_u + ((k0 + trow) * BSTR
                                   + wn * 64 + 16 * jp + tcol) * 2);
                bf[2 * jp][0]     = t4[0];
                bf[2 * jp][1]     = t4[1];
                bf[2 * jp + 1][0] = t4[2];
                bf[2 * jp + 1][1] = t4[3];
            }
#pragma unroll
            for (int i = 0; i < 2; i++)
#pragma unroll
                for (int j = 0; j < 8; j++)
                    mma_f16(acc[i][j], af[i], bf[j]);
        }
    }

    float*  Cf = (float*)CoutV;
    __half* Ch = (__half*)CoutV;
#pragma unroll
    for (int i = 0; i < 2; i++) {
#pragma unroll
        for (int hr = 0; hr < 2; hr++) {
            int r = row0 + wm * 32 + i * 16 + hr * 8 + gid;
#pragma unroll
            for (int j = 0; j < 8; j++) {
                int cI = col0 + wn * 64 + j * 8 + 2 * tid4;
                float v0 = acc[i][j][hr * 2];
                float v1 = acc[i][j][hr * 2 + 1];
                if (BIAS) {
                    float2 bi = *(const float2*)&bias[cI];
                    v0 += bi.x; v1 += bi.y;
                }
                if (RES) {
                    float2 rv = *(const float2*)&res[(size_t)r * N + cI];
                    v0 += rv.x; v1 += rv.y;
                }
                if (RELU) { v0 = fmaxf(v0, 0.f); v1 = fmaxf(v1, 0.f); }
                if (OUTH) {
                    *(__half2*)&Ch[(size_t)r * N + cI] = __floats2half2_rn(v0, v1);
                } else {
                    *(float2*)&Cf[(size_t)r * N + cI] = make_float2(v0, v1);
                }
            }
        }
    }
}

// ---------------------------------------------------------------------------
// Causal flash attention (Round-12 PASS, unchanged).
// ---------------------------------------------------------------------------
#define AST 72
#define ATT_SMEM ((64 + 128 + 128) * AST * 2)

__global__ __launch_bounds__(128, 2)
void attn_f16_kernel(const __half* __restrict__ qkv,
                     __half* __restrict__ outp) {
    extern __shared__ __half sha[];
    __half* Qs = sha;                   // [64][AST]
    __half* Ks = Qs + 64 * AST;         // [2][64][AST]  rows = s, cols = d
    __half* Vs = Ks + 2 * 64 * AST;     // [2][64][AST]  rows = s, cols = d

    const int qt = (int)gridDim.x - 1 - (int)blockIdx.x;   // heavy first
    const int h = blockIdx.y, b = blockIdx.z;
    const int t0 = qt * 64;
    const int tid  = threadIdx.x;
    const int lane = tid & 31;
    const int warp = tid >> 5;
    const int gid  = lane >> 2;
    const int tid4 = lane & 3;
    const unsigned FULL = 0xffffffffu;

    const int lrow = lane & 7;
    const int q    = lane >> 3;
    const int arow = (q & 1) * 8 + lrow;
    const int akof = (q >> 1) * 8;
    const int brow = (q >> 1) * 8 + lrow;
    const int bkof = (q & 1) * 8;
    const int trow = (q & 1) * 8 + lrow;     // trans (V)
    const int tcol = (q >> 1) * 8;

    const uint32_t sm_u = (uint32_t)__cvta_generic_to_shared(sha);
    const uint32_t Qs_u = sm_u;
    const uint32_t Ks_u = sm_u + 64 * AST * 2;
    const uint32_t Vs_u = Ks_u + 2 * 64 * AST * 2;

    const __half* qb = qkv + (size_t)(b * Tt) * QKV_N + h * DHd;
    const __half* kb = qkv + (size_t)(b * Tt) * QKV_N + Cc + h * DHd;
    const __half* vb = qkv + (size_t)(b * Tt) * QKV_N + 2 * Cc + h * DHd;

#pragma unroll
    for (int qq = 0; qq < 4; qq++) {
        int id  = tid + 128 * qq;
        int row = id >> 3;
        int c8  = (id & 7) * 8;
        cp_async16(&Qs[row * AST + c8], qb + (size_t)(t0 + row) * QKV_N + c8);
        cp_async16(&Ks[row * AST + c8], kb + (size_t)row * QKV_N + c8);
        cp_async16(&Vs[row * AST + c8], vb + (size_t)row * QKV_N + c8);
    }
    cp_async_commit();
    cp_async_wait0();
    __syncthreads();

    uint32_t qa[4][4];
#pragma unroll
    for (int ks = 0; ks < 4; ks++)
        ldsm4(qa[ks], Qs_u + ((16 * warp + arow) * AST + 16 * ks + akof) * 2);

    float m0 = -1e30f, m1 = -1e30f, l0 = 0.f, l1 = 0.f;
    float o[8][4];
#pragma unroll
    for (int j = 0; j < 8; j++)
#pragma unroll
        for (int qq = 0; qq < 4; qq++) o[j][qq] = 0.f;

    const int nt = qt + 1;
    for (int it = 0; it < nt; ++it) {
        const int buf = it & 1;
        const uint32_t Kb_u = Ks_u + buf * 64 * AST * 2;
        const uint32_t Vb_u = Vs_u + buf * 64 * AST * 2;

        cp_async_wait0();
        __syncthreads();

        if (it + 1 < nt) {
            const int s0 = (it + 1) * 64;
            __half* Kn = Ks + (buf ^ 1) * 64 * AST;
            __half* Vn = Vs + (buf ^ 1) * 64 * AST;
#pragma unroll
            for (int qq = 0; qq < 4; qq++) {
                int id  = tid + 128 * qq;
                int row = id >> 3;
                int c8  = (id & 7) * 8;
                cp_async16(&Kn[row * AST + c8],
                           kb + (size_t)(s0 + row) * QKV_N + c8);
                cp_async16(&Vn[row * AST + c8],
                           vb + (size_t)(s0 + row) * QKV_N + c8);
            }
            cp_async_commit();
        }

        // ---- S = Q K^T ----
        float sc[8][4];
#pragma unroll
        for (int j = 0; j < 8; j++)
#pragma unroll
            for (int qq = 0; qq < 4; qq++) sc[j][qq] = 0.f;
#pragma unroll
        for (int ks = 0; ks < 4; ks++) {
            uint32_t kf[8][2];
#pragma unroll
            for (int jp = 0; jp < 4; jp++) {
                uint32_t t4[4];
                ldsm4(t4, Kb_u + ((16 * jp + brow) * AST + 16 * ks + bkof) * 2);
                kf[2 * jp][0]     = t4[0];
                kf[2 * jp][1]     = t4[1];
                kf[2 * jp + 1][0] = t4[2];
                kf[2 * jp + 1][1] = t4[3];
            }
#pragma unroll
            for (int j = 0; j < 8; j++)
                mma_f16(sc[j], qa[ks], kf[j]);
        }

        if (it == qt) {
            int r0 = 16 * warp + gid;
#pragma unroll
            for (int j = 0; j < 8; j++) {
                int c0 = 8 * j + 2 * tid4;
                if (c0     > r0)     sc[j][0] = -1e30f;
                if (c0 + 1 > r0)     sc[j][1] = -1e30f;
                if (c0     > r0 + 8) sc[j][2] = -1e30f;
                if (c0 + 1 > r0 + 8) sc[j][3] = -1e30f;
            }
        }

        // ---- online softmax ----
        float mx0 = -1e30f, mx1 = -1e30f;
#pragma unroll
        for (int j = 0; j < 8; j++) {
            mx0 = fmaxf(mx0, fmaxf(sc[j][0], sc[j][1]));
            mx1 = fmaxf(mx1, fmaxf(sc[j][2], sc[j][3]));
        }
        mx0 = fmaxf(mx0, __shfl_xor_sync(FULL, mx0, 1));
        mx0 = fmaxf(mx0, __shfl_xor_sync(FULL, mx0, 2));
        mx1 = fmaxf(mx1, __shfl_xor_sync(FULL, mx1, 1));
        mx1 = fmaxf(mx1, __shfl_xor_sync(FULL, mx1, 2));
        float mn0 = fmaxf(m0, mx0), mn1 = fmaxf(m1, mx1);
        float sum0 = 0.f, sum1 = 0.f;
#pragma unroll
        for (int j = 0; j < 8; j++) {
            sc[j][0] = __expf(sc[j][0] - mn0);
            sc[j][1] = __expf(sc[j][1] - mn0);
            sc[j][2] = __expf(sc[j][2] - mn1);
            sc[j][3] = __expf(sc[j][3] - mn1);
            sum0 += sc[j][0] + sc[j][1];
            sum1 += sc[j][2] + sc[j][3];
        }
        sum0 += __shfl_xor_sync(FULL, sum0, 1);
        sum0 += __shfl_xor_sync(FULL, sum0, 2);
        sum1 += __shfl_xor_sync(FULL, sum1, 1);
        sum1 += __shfl_xor_sync(FULL, sum1, 2);
        float c0 = __expf(m0 - mn0), c1 = __expf(m1 - mn1);
        l0 = l0 * c0 + sum0;
        l1 = l1 * c1 + sum1;
        m0 = mn0; m1 = mn1;
#pragma unroll
        for (int j = 0; j < 8; j++) {
            o[j][0] *= c0; o[j][1] *= c0;
            o[j][2] *= c1; o[j][3] *= c1;
        }

        // ---- O += P V : P from registers; V frags via ldmatrix.trans ----
#pragma unroll
        for (int ks = 0; ks < 4; ks++) {
            uint32_t pa[4];
            pa[0] = pack_h2(sc[2 * ks][0],     sc[2 * ks][1]);
            pa[1] = pack_h2(sc[2 * ks][2],     sc[2 * ks][3]);
            pa[2] = pack_h2(sc[2 * ks + 1][0], sc[2 * ks + 1][1]);
            pa[3] = pack_h2(sc[2 * ks + 1][2], sc[2 * ks + 1][3]);
            uint32_t vf[8][2];
#pragma unroll
            for (int jp = 0; jp < 4; jp++) {
                uint32_t t4[4];
                ldsm4t(t4, Vb_u + ((16 * ks + trow) * AST + 16 * jp + tcol) * 2);
                vf[2 * jp][0]     = t4[0];
                vf[2 * jp][1]     = t4[1];
                vf[2 * jp + 1][0] = t4[2];
                vf[2 * jp + 1][1] = t4[3];
            }
#pragma unroll
            for (int j = 0; j < 8; j++)
                mma_f16(o[j], pa, vf[j]);
        }
    }

    float inv0 = 1.f / l0, inv1 = 1.f / l1;
    int r0 = t0 + 16 * warp + gid;
#pragma unroll
    for (int j = 0; j < 8; j++) {
        int cI = h * DHd + 8 * j + 2 * tid4;
        __half2 v0 = __floats2half2_rn(o[j][0] * inv0, o[j][1] * inv0);
        __half2 v1 = __floats2half2_rn(o[j][2] * inv1, o[j][3] * inv1);
        *(__half2*)&outp[(size_t)(b * Tt + r0) * Cc + cI]     = v0;
        *(__half2*)&outp[(size_t)(b * Tt + r0 + 8) * Cc + cI] = v1;
    }
}

// ---------------------------------------------------------------------------
// Launch
// ---------------------------------------------------------------------------
extern "C" void kernel_launch(void* const* d_in, const int* in_sizes, int n_in,
                              void* d_out, int out_size) {
    const float* x      = (const float*)d_in[0];
    const float* Wq     = (const float*)d_in[1];
    const float* Wk     = (const float*)d_in[2];
    const float* Wv     = (const float*)d_in[3];
    const float* Wo     = (const float*)d_in[4];
    const float* bo     = (const float*)d_in[5];
    const float* W1     = (const float*)d_in[6];
    const float* b1     = (const float*)d_in[7];
    const float* W2     = (const float*)d_in[8];
    const float* b2     = (const float*)d_in[9];
    const float* gamma1 = (const float*)d_in[10];
    const float* beta1  = (const float*)d_in[11];
    const float* gamma2 = (const float*)d_in[12];
    const float* beta2  = (const float*)d_in[13];
    float* out = (float*)d_out;

    __half *p_x1, *p_qkv, *p_attn, *p_x2, *p_h, *p_wqkv, *p_wo, *p_w1, *p_w2;
    float *p_y;
    cudaGetSymbolAddress((void**)&p_x1,   g_x1);
    cudaGetSymbolAddress((void**)&p_qkv,  g_qkv);
    cudaGetSymbolAddress((void**)&p_attn, g_attn);
    cudaGetSymbolAddress((void**)&p_y,    g_y);
    cudaGetSymbolAddress((void**)&p_x2,   g_x2);
    cudaGetSymbolAddress((void**)&p_h,    g_h);
    cudaGetSymbolAddress((void**)&p_wqkv, g_wqkv);
    cudaGetSymbolAddress((void**)&p_wo,   g_wo);
    cudaGetSymbolAddress((void**)&p_w1,   g_w1);
    cudaGetSymbolAddress((void**)&p_w2,   g_w2);

    cudaFuncSetAttribute(gemm_f16_kernel<false, false, false, true>,
                         cudaFuncAttributeMaxDynamicSharedMemorySize, GEMM_SMEM);
    cudaFuncSetAttribute(gemm_f16_kernel<true, false, true, false>,
                         cudaFuncAttributeMaxDynamicSharedMemorySize, GEMM_SMEM);
    cudaFuncSetAttribute(gemm_f16_kernel<true, true, false, true>,
                         cudaFuncAttributeMaxDynamicSharedMemorySize, GEMM_SMEM);
    cudaFuncSetAttribute(attn_f16_kernel,
                         cudaFuncAttributeMaxDynamicSharedMemorySize, ATT_SMEM);

    // 0) weight prep: straight fp32->fp16 copies (no transposes)
    pack_qkv_kn_kernel<<<(Cc * QKV_N / 4 + 255) / 256, 256>>>(Wq, Wk, Wv);
    round_h_kernel<<<(Cc * Cc / 4 + 255) / 256, 256>>>(Wo, p_wo, Cc * Cc / 4);
    round_h_kernel<<<(Cc * FFN_N / 4 + 255) / 256, 256>>>(W1, p_w1, Cc * FFN_N / 4);
    round_h_kernel<<<(FFN_N * Cc / 4 + 255) / 256, 256>>>(W2, p_w2, FFN_N * Cc / 4);

    // 1) LN1 -> fp16
    {
        dim3 grid(Cc / 32, Bb), block(32, 32);
        ln_axis1_kernel<<<grid, block>>>(x, gamma1, beta1, p_x1);
    }

    // 2) fused QKV GEMM -> fp16 qkv
    {
        dim3 grid(QKV_N / 128, Mrows / 128);
        gemm_f16_kernel<false, false, false, true><<<grid, 256, GEMM_SMEM>>>(
            p_x1, p_wqkv, nullptr, nullptr, p_qkv, Mrows, QKV_N, Cc);
    }

    // 3) attention
    {
        dim3 grid(Tt / 64, Hh, Bb);
        attn_f16_kernel<<<grid, 128, ATT_SMEM>>>(p_qkv, p_attn);
    }

    // 4) output projection + bias + residual -> y fp32
    {
        dim3 grid(Cc / 128, Mrows / 128);
        gemm_f16_kernel<true, false, true, false><<<grid, 256, GEMM_SMEM>>>(
            p_attn, p_wo, bo, x, p_y, Mrows, Cc, Cc);
    }

    // 5) LN2 -> fp16
    {
        dim3 grid(Cc / 32, Bb), block(32, 32);
        ln_axis1_kernel<<<grid, block>>>(p_y, gamma2, beta2, p_x2);
    }

    // 6) FFN1: h = relu(x2 @ W1 + b1) -> fp16
    {
        dim3 grid(FFN_N / 128, Mrows / 128);
        gemm_f16_kernel<true, true, false, true><<<grid, 256, GEMM_SMEM>>>(
            p_x2, p_w1, b1, nullptr, p_h, Mrows, FFN_N, Cc);
    }

    // 7) FFN2: out = y + h @ W2 + b2 -> fp32
    {
        dim3 grid(Cc / 128, Mrows / 128);
        gemm_f16_kernel<true, false, true, false><<<grid, 256, GEMM_SMEM>>>(
            p_h, p_w2, b2, p_y, out, Mrows, Cc, FFN_N);
    }
}